// round 15
// baseline (speedup 1.0000x reference)
#include <cuda_runtime.h>

#define BB 16
#define NN 4096
#define S1V 512
#define S2V 256
#define KV 32
#define EPSF 1e-5f

typedef unsigned long long ull;

// ---------------- f32x2 packed-FMA helpers ----------------
__device__ __forceinline__ void ffma2(ull& acc, ull a, ull b) {
    asm volatile("fma.rn.f32x2 %0, %1, %2, %0;" : "+l"(acc) : "l"(a), "l"(b));
}
__device__ __forceinline__ ull splat2(float x) {
    ull r;
    asm("mov.b64 %0, {%1, %1};" : "=l"(r) : "f"(x));
    return r;
}
__device__ __forceinline__ float2 unpk(ull v) {
    float lo, hi;
    asm("mov.b64 {%0, %1}, %2;" : "=f"(lo), "=f"(hi) : "l"(v));
    return make_float2(lo, hi);
}

// float -> order-preserving uint (handles negatives)
__device__ __forceinline__ unsigned fkey(float v) {
    unsigned u = __float_as_uint(v);
    return (u & 0x80000000u) ? ~u : (u | 0x80000000u);
}
__device__ __forceinline__ float funkey(unsigned k) {
    unsigned u = (k & 0x80000000u) ? (k ^ 0x80000000u) : ~k;
    return __uint_as_float(u);
}

// ---------------- scratch ----------------
__device__ __align__(16) float g_zbuf[33554432];
__device__ __align__(16) float g_f[BB * NN * 64];
__device__ __align__(16) float g_f1[BB * S1V * 128];
__device__ __align__(16) float g_cfeat1[BB * S1V * 64];
__device__ __align__(16) float g_cfeat2[BB * S2V * 128];
__device__ __align__(16) float g_c1out[BB * S1V * 128];
__device__ __align__(16) float g_c2out[BB * S2V * 256];
__device__ __align__(16) float g_wdiff1[128 * 64];
__device__ __align__(16) float g_wdiff2[256 * 128];
__device__ __align__(16) float g_pmax[1048576];
__device__ __align__(16) float g_pmin[1048576];
__device__ __align__(16) float4 g_pk1[BB * NN];     // (x,y,z,norm2)
__device__ __align__(16) float4 g_pk2[BB * S1V];
__device__ int   g_fidx1[BB * S1V], g_fidx2[BB * S2V];
__device__ int   g_knn1[BB * S1V * KV], g_knn2[BB * S2V * KV];
__device__ __align__(16) float g_sum[256], g_sumsq[256];
__device__ __align__(16) float g_scale[256], g_shift[256];

__device__ __forceinline__ float* buf_sel(int w) {
    switch (w) {
        case 0: return g_zbuf;
        case 2: return g_f;
        case 3: return g_cfeat1;
        case 4: return g_cfeat2;
        case 5: return g_c1out;
        case 6: return g_c2out;
        case 7: return g_wdiff1;
        case 8: return g_wdiff2;
        case 9: return g_f1;
    }
    return g_zbuf;
}

// ---------------- coords prep (packed) ----------------
__global__ void prep_coords(const float* __restrict__ x) {
    int i = blockIdx.x * 256 + threadIdx.x;
    int b = i >> 12, n = i & 4095;
    const float* xb = x + (size_t)b * 3 * NN;
    float X = xb[n], Y = xb[NN + n], Z = xb[2 * NN + n];
    g_pk1[i] = make_float4(X, Y, Z, X * X + Y * Y + Z * Z);
}

// ---------------- point_cbr stage 1 (fused stats) ----------------
__global__ void cbr1_kernel(const float* __restrict__ x, const float* __restrict__ w1) {
    __shared__ float ws[192];
    int tid = threadIdx.x;
    if (tid < 192) ws[tid] = w1[tid];
    __syncthreads();
    int o = tid & 63;
    float wa = ws[o * 3 + 0], wb = ws[o * 3 + 1], wc = ws[o * 3 + 2];
    float s = 0.f, q = 0.f;
    for (int i = blockIdx.x * 256 + tid; i < BB * NN * 64; i += 512 * 256) {
        int r = i >> 6;
        int b = r >> 12, n = r & 4095;
        const float* xb = x + (size_t)b * 3 * NN;
        float v = wa * xb[n] + wb * xb[NN + n] + wc * xb[2 * NN + n];
        g_zbuf[i] = v;
        s += v; q += v * v;
    }
    __shared__ float bs[256], bq[256];
    bs[tid] = s; bq[tid] = q;
    __syncthreads();
    if (tid < 64) {
        for (int j = tid + 64; j < 256; j += 64) { s += bs[j]; q += bq[j]; }
        atomicAdd(&g_sum[tid], s);
        atomicAdd(&g_sumsq[tid], q);
    }
}

// ---------------- point_cbr stage 2 (persistent blocks, fused stats) ----------------
__global__ void cbr2_kernel(const float* __restrict__ w2) {
    __shared__ float ys[4][64];
    __shared__ float wst[64 * 64];
    int tid = threadIdx.x;
    for (int j = tid; j < 4096; j += 256) {
        int o = j >> 6, c = j & 63;
        wst[c * 64 + o] = w2[j];
    }
    int rl = tid >> 6, o = tid & 63;
    float scl = g_scale[o], shf = g_shift[o];
    float s = 0.f, q = 0.f;
    for (int it = 0; it < 32; it++) {
        int r0 = (blockIdx.x * 32 + it) * 4;
        __syncthreads();
        {
            float v = g_zbuf[r0 * 64 + tid];
            v = fmaxf(v * scl + shf, 0.f);
            ((float*)ys)[tid] = v;
        }
        __syncthreads();
        float acc = 0.f;
#pragma unroll 16
        for (int c = 0; c < 64; c++) acc += ys[rl][c] * wst[c * 64 + o];
        g_f[(r0 + rl) * 64 + o] = acc;
        s += acc; q += acc * acc;
    }
    __shared__ float bs[256], bq[256];
    bs[tid] = s; bq[tid] = q;
    __syncthreads();
    if (tid < 64) {
        for (int j = tid + 64; j < 256; j += 64) { s += bs[j]; q += bq[j]; }
        atomicAdd(&g_sum[tid], s);
        atomicAdd(&g_sumsq[tid], q);
    }
}

// ---------------- finalize (zeroes accumulators for next use) ----------------
__global__ void finalize_stats(const float* __restrict__ g, const float* __restrict__ bias,
                               float invR, int O) {
    int o = threadIdx.x;   // 256
    float su = g_sum[o], sq = g_sumsq[o];
    g_sum[o] = 0.f; g_sumsq[o] = 0.f;
    if (o < O) {
        float m = su * invR;
        float v = sq * invR - m * m;
        float rstd = rsqrtf(v + EPSF);
        float sc = g[o] * rstd;
        g_scale[o] = sc;
        g_shift[o] = bias[o] - m * sc;
    }
}

// ---------------- FPS (bit-exact; REDUX argmax; smem far-coord broadcast) ----------------
template <int NPTS, int NSAMP, int TPB, int TSH, int STAGE>
__global__ void fps_kernel() {
    constexpr int PPT = NPTS / TPB;
    constexpr int NW = TPB / 32;
    const float4* pk = (STAGE == 0) ? g_pk1 : g_pk2;
    int* fidx = (STAGE == 0) ? g_fidx1 : g_fidx2;
    int b = blockIdx.x, tid = threadIdx.x;
    int lane = tid & 31;
    const float4* bp = pk + b * NPTS;
    float px[PPT], py[PPT], pz[PPT], dist[PPT];
#pragma unroll
    for (int t = 0; t < PPT; t++) {
        float4 p = bp[tid + t * TPB];
        px[t] = p.x; py[t] = p.y; pz[t] = p.z;
        dist[t] = 1e10f;
    }
    __shared__ unsigned wv[NW];
    __shared__ unsigned wi[NW];
    __shared__ float s_fx, s_fy, s_fz;
    if (tid == 0) { s_fx = px[0]; s_fy = py[0]; s_fz = pz[0]; }
    __syncthreads();
    int far = 0;
    for (int s = 0; s < NSAMP; s++) {
        if (tid == 0) fidx[b * NSAMP + s] = far;
        float fx = s_fx, fy = s_fy, fz = s_fz;
        float bv = -1.0f; int bi = 0x7fffffff;
#pragma unroll
        for (int t = 0; t < PPT; t++) {
            float dx = __fsub_rn(px[t], fx);
            float dy = __fsub_rn(py[t], fy);
            float dz = __fsub_rn(pz[t], fz);
            float d = __fadd_rn(__fadd_rn(__fmul_rn(dx, dx), __fmul_rn(dy, dy)), __fmul_rn(dz, dz));
            float nd = fminf(dist[t], d);
            dist[t] = nd;
            int n = tid + t * TPB;
            if (nd > bv) { bv = nd; bi = n; }   // lowest n on tie within thread
        }
        // warp argmax via REDUX (dist >= 0 so float bits are uint-monotonic)
        unsigned uv = __float_as_uint(bv);
        unsigned vmax = __reduce_max_sync(0xffffffffu, uv);
        unsigned cand = (uv == vmax) ? (unsigned)bi : 0xffffffffu;
        unsigned imin = __reduce_min_sync(0xffffffffu, cand);
        if (lane == 0) { wv[tid >> 5] = vmax; wi[tid >> 5] = imin; }
        __syncthreads();
        // every warp computes the block argmax redundantly
        unsigned uv2 = (lane < NW) ? wv[lane] : 0u;
        unsigned vm2 = __reduce_max_sync(0xffffffffu, uv2);
        unsigned c2 = (lane < NW && uv2 == vm2) ? wi[lane] : 0xffffffffu;
        far = (int)__reduce_min_sync(0xffffffffu, c2);
        // owner thread broadcasts far coords from its registers
        if (tid == (far & (TPB - 1))) {
            int t = far >> TSH;
            s_fx = px[t]; s_fy = py[t]; s_fz = pz[t];
        }
        __syncthreads();
    }
}

// ---------------- gather sampled sg1 coords (packed) ----------------
__global__ void gather_c2() {
    int i = blockIdx.x * 256 + threadIdx.x;   // BB*S1V
    int b = i >> 9;
    int id = g_fidx1[i];
    g_pk2[i] = g_pk1[b * NN + id];
}

// ---------------- KNN: warp top-32, REDUX insertion, packed loads ----------------
template <int NPTS, int S, int STAGE>
__global__ void knn_kernel() {
    const float4* pk = (STAGE == 0) ? g_pk1 : g_pk2;
    const int* fidx = (STAGE == 0) ? g_fidx1 : g_fidx2;
    int* knn = (STAGE == 0) ? g_knn1 : g_knn2;

    int gw = (blockIdx.x * blockDim.x + threadIdx.x) >> 5;
    int lane = threadIdx.x & 31;
    int b = gw / S;
    const float4* bp = pk + b * NPTS;
    int ci = fidx[gw];
    float4 f = bp[ci];
    float fx = f.x, fy = f.y, fz = f.z;

    // relative distance: d = ||p||^2 - 2<f,p>  (constant ||f||^2 dropped; order preserved)
    auto distf = [&](float4 p) {
        float dot = fmaf(fx, p.x, fmaf(fy, p.y, fz * p.z));
        return fmaf(-2.0f, dot, p.w);
    };

    float bd = distf(bp[lane]);
    int bidx = lane;

    float kv; int kl;
    auto rered = [&]() {
        unsigned k = fkey(bd);
        unsigned vmax = __reduce_max_sync(0xffffffffu, k);
        unsigned cand = (k == vmax) ? (unsigned)lane : 63u;
        kl = (int)__reduce_min_sync(0xffffffffu, cand);
        kv = funkey(vmax);
    };
    rered();

    for (int base = 32; base < NPTS; base += 32) {
        float4 p = bp[base + lane];
        float d = distf(p);
        unsigned m = __ballot_sync(0xffffffffu, d < kv);
        while (m) {
            int src = __ffs(m) - 1;
            m &= m - 1;
            float dc = __shfl_sync(0xffffffffu, d, src);
            if (dc < kv) {
                if (lane == kl) { bd = dc; bidx = base + src; }
                rered();
            }
        }
    }
    knn[gw * KV + lane] = bidx;
}

// ---------------- smem swizzle ----------------
__device__ __forceinline__ int swz(int col) {
    int blk = col >> 5;
    return (blk << 5) + (((col & 31) + (blk << 2)) & 31);
}

// ---------------- plain swizzled double-buffered SGEMM (FFMA2 core) ----------------
template <int CIN, int WS, bool BNA>
__global__ __launch_bounds__(256) void gemm_k(int asel, const float* __restrict__ Wp_in,
                                              int wsel, int csel, int O) {
    const float* A = buf_sel(asel);
    const float* W = Wp_in ? Wp_in : buf_sel(wsel);
    float* C = buf_sel(csel);
    __shared__ float As[2][8 * 132];
    __shared__ float Bs[2][8 * 132];
    int tid = threadIdx.x;
    int brow = blockIdx.x * 128, bcol = blockIdx.y * 128;
    int tx = tid & 15, ty = tid >> 4;
    int lr = tid >> 1, lc = (tid & 1) * 4;
    const float* Ap = A + (size_t)(brow + lr) * CIN + lc;
    const float* Wp = W + (size_t)(bcol + lr) * WS + lc;
    int wp = swz(lr);
    int sa0 = swz(ty * 8), sa1 = swz(ty * 8 + 4);
    int sb0 = swz(tx * 8), sb1 = swz(tx * 8 + 4);

    float4 av = *(const float4*)Ap;
    float4 wv = *(const float4*)Wp;
    if (BNA) {
        float4 sc = *(const float4*)&g_scale[lc];
        float4 sh = *(const float4*)&g_shift[lc];
        av.x = fmaxf(av.x * sc.x + sh.x, 0.f);
        av.y = fmaxf(av.y * sc.y + sh.y, 0.f);
        av.z = fmaxf(av.z * sc.z + sh.z, 0.f);
        av.w = fmaxf(av.w * sc.w + sh.w, 0.f);
    }
    As[0][(lc + 0) * 132 + wp] = av.x; As[0][(lc + 1) * 132 + wp] = av.y;
    As[0][(lc + 2) * 132 + wp] = av.z; As[0][(lc + 3) * 132 + wp] = av.w;
    Bs[0][(lc + 0) * 132 + wp] = wv.x; Bs[0][(lc + 1) * 132 + wp] = wv.y;
    Bs[0][(lc + 2) * 132 + wp] = wv.z; Bs[0][(lc + 3) * 132 + wp] = wv.w;
    __syncthreads();

    ull acc2[8][4];
#pragma unroll
    for (int i = 0; i < 8; i++)
#pragma unroll
        for (int j = 0; j < 4; j++) acc2[i][j] = 0ull;

    constexpr int NIT = CIN / 8;
#pragma unroll 2
    for (int it = 0; it < NIT; it++) {
        int cur = it & 1;
        float4 av2, wv2;
        if (it + 1 < NIT) {
            av2 = *(const float4*)(Ap + (it + 1) * 8);
            wv2 = *(const float4*)(Wp + (it + 1) * 8);
            if (BNA) {
                float4 sc = *(const float4*)&g_scale[(it + 1) * 8 + lc];
                float4 sh = *(const float4*)&g_shift[(it + 1) * 8 + lc];
                av2.x = fmaxf(av2.x * sc.x + sh.x, 0.f);
                av2.y = fmaxf(av2.y * sc.y + sh.y, 0.f);
                av2.z = fmaxf(av2.z * sc.z + sh.z, 0.f);
                av2.w = fmaxf(av2.w * sc.w + sh.w, 0.f);
            }
        }
#pragma unroll
        for (int k = 0; k < 8; k++) {
            float4 a0 = *(const float4*)&As[cur][k * 132 + sa0];
            float4 a1 = *(const float4*)&As[cur][k * 132 + sa1];
            ulonglong2 bp0 = *(const ulonglong2*)&Bs[cur][k * 132 + sb0];
            ulonglong2 bp1 = *(const ulonglong2*)&Bs[cur][k * 132 + sb1];
            float a[8] = {a0.x, a0.y, a0.z, a0.w, a1.x, a1.y, a1.z, a1.w};
            ull bp[4] = {bp0.x, bp0.y, bp1.x, bp1.y};
#pragma unroll
            for (int i = 0; i < 8; i++) {
                ull as = splat2(a[i]);
#pragma unroll
                for (int j = 0; j < 4; j++) ffma2(acc2[i][j], as, bp[j]);
            }
        }
        if (it + 1 < NIT) {
            int nxt = 1 - cur;
            As[nxt][(lc + 0) * 132 + wp] = av2.x; As[nxt][(lc + 1) * 132 + wp] = av2.y;
            As[nxt][(lc + 2) * 132 + wp] = av2.z; As[nxt][(lc + 3) * 132 + wp] = av2.w;
            Bs[nxt][(lc + 0) * 132 + wp] = wv2.x; Bs[nxt][(lc + 1) * 132 + wp] = wv2.y;
            Bs[nxt][(lc + 2) * 132 + wp] = wv2.z; Bs[nxt][(lc + 3) * 132 + wp] = wv2.w;
            __syncthreads();
        }
    }
#pragma unroll
    for (int i = 0; i < 8; i++) {
        int r = brow + ty * 8 + i;
        float4* cp = (float4*)(C + (size_t)r * O + bcol + tx * 8);
        float2 p0 = unpk(acc2[i][0]), p1 = unpk(acc2[i][1]);
        float2 p2 = unpk(acc2[i][2]), p3 = unpk(acc2[i][3]);
        cp[0] = make_float4(p0.x, p0.y, p1.x, p1.y);
        cp[1] = make_float4(p2.x, p2.y, p3.x, p3.y);
    }
}

// ---------------- FUSED layer-2 GEMM (FFMA2 core) ----------------
template <int CIN, int STAGE>
__global__ __launch_bounds__(256) void gemm2_fused(const float* __restrict__ W) {
    const float* G = g_zbuf;
    const float* C = (STAGE == 0) ? g_c1out : g_c2out;
    const int* knn = (STAGE == 0) ? g_knn1 : g_knn2;
    constexpr int NPTS = (STAGE == 0) ? NN : S1V;
    constexpr int BSH = (STAGE == 0) ? 9 : 8;

    __shared__ float As[2][8 * 132];
    __shared__ float Bs[2][8 * 132];
    int tid = threadIdx.x;
    int brow = blockIdx.x * 128, bcol = blockIdx.y * 128;
    int tx = tid & 15, ty = tid >> 4;
    int lr = tid >> 1, lc = (tid & 1) * 4;

    int grow = brow + lr;
    int nb = knn[grow];
    int bs = grow >> 5;
    int b = bs >> BSH;
    const float* Gp = G + ((size_t)(b * NPTS + nb)) * CIN + lc;
    const float* Cp = C + (size_t)bs * CIN + lc;
    const float* Wp = W + (size_t)(bcol + lr) * CIN + lc;
    int wp = swz(lr);
    int sa0 = swz(ty * 8), sa1 = swz(ty * 8 + 4);
    int sb0 = swz(tx * 8), sb1 = swz(tx * 8 + 4);

    {
        float4 gv = *(const float4*)Gp;
        float4 cv = *(const float4*)Cp;
        float4 wv = *(const float4*)Wp;
        float4 sc = *(const float4*)&g_scale[lc];
        float4 sh = *(const float4*)&g_shift[lc];
        float ax = fmaxf((gv.x + cv.x) * sc.x + sh.x, 0.f);
        float ay = fmaxf((gv.y + cv.y) * sc.y + sh.y, 0.f);
        float az = fmaxf((gv.z + cv.z) * sc.z + sh.z, 0.f);
        float aw = fmaxf((gv.w + cv.w) * sc.w + sh.w, 0.f);
        As[0][(lc + 0) * 132 + wp] = ax; As[0][(lc + 1) * 132 + wp] = ay;
        As[0][(lc + 2) * 132 + wp] = az; As[0][(lc + 3) * 132 + wp] = aw;
        Bs[0][(lc + 0) * 132 + wp] = wv.x; Bs[0][(lc + 1) * 132 + wp] = wv.y;
        Bs[0][(lc + 2) * 132 + wp] = wv.z; Bs[0][(lc + 3) * 132 + wp] = wv.w;
    }
    __syncthreads();

    ull acc2[8][4];
#pragma unroll
    for (int i = 0; i < 8; i++)
#pragma unroll
        for (int j = 0; j < 4; j++) acc2[i][j] = 0ull;

    constexpr int NIT = CIN / 8;
#pragma unroll 2
    for (int it = 0; it < NIT; it++) {
        int cur = it & 1;
        float axp, ayp, azp, awp;
        float4 wv2;
        if (it + 1 < NIT) {
            float4 gv = *(const float4*)(Gp + (it + 1) * 8);
            float4 cv = *(const float4*)(Cp + (it + 1) * 8);
            wv2 = *(const float4*)(Wp + (it + 1) * 8);
            float4 sc = *(const float4*)&g_scale[(it + 1) * 8 + lc];
            float4 sh = *(const float4*)&g_shift[(it + 1) * 8 + lc];
            axp = fmaxf((gv.x + cv.x) * sc.x + sh.x, 0.f);
            ayp = fmaxf((gv.y + cv.y) * sc.y + sh.y, 0.f);
            azp = fmaxf((gv.z + cv.z) * sc.z + sh.z, 0.f);
            awp = fmaxf((gv.w + cv.w) * sc.w + sh.w, 0.f);
        }
#pragma unroll
        for (int k = 0; k < 8; k++) {
            float4 a0 = *(const float4*)&As[cur][k * 132 + sa0];
            float4 a1 = *(const float4*)&As[cur][k * 132 + sa1];
            ulonglong2 bp0 = *(const ulonglong2*)&Bs[cur][k * 132 + sb0];
            ulonglong2 bp1 = *(const ulonglong2*)&Bs[cur][k * 132 + sb1];
            float a[8] = {a0.x, a0.y, a0.z, a0.w, a1.x, a1.y, a1.z, a1.w};
            ull bp[4] = {bp0.x, bp0.y, bp1.x, bp1.y};
#pragma unroll
            for (int i = 0; i < 8; i++) {
                ull as = splat2(a[i]);
#pragma unroll
                for (int j = 0; j < 4; j++) ffma2(acc2[i][j], as, bp[j]);
            }
        }
        if (it + 1 < NIT) {
            int nxt = 1 - cur;
            As[nxt][(lc + 0) * 132 + wp] = axp; As[nxt][(lc + 1) * 132 + wp] = ayp;
            As[nxt][(lc + 2) * 132 + wp] = azp; As[nxt][(lc + 3) * 132 + wp] = awp;
            Bs[nxt][(lc + 0) * 132 + wp] = wv2.x; Bs[nxt][(lc + 1) * 132 + wp] = wv2.y;
            Bs[nxt][(lc + 2) * 132 + wp] = wv2.z; Bs[nxt][(lc + 3) * 132 + wp] = wv2.w;
            __syncthreads();
        }
    }

    float tmax[8], tmin[8], tsum[8], tsq[8];
#pragma unroll
    for (int j = 0; j < 8; j++) { tmax[j] = -1e30f; tmin[j] = 1e30f; tsum[j] = 0.f; tsq[j] = 0.f; }
#pragma unroll
    for (int i = 0; i < 8; i++)
#pragma unroll
        for (int jp = 0; jp < 4; jp++) {
            float2 p = unpk(acc2[i][jp]);
            int j0 = jp * 2;
            tmax[j0] = fmaxf(tmax[j0], p.x);
            tmin[j0] = fminf(tmin[j0], p.x);
            tsum[j0] += p.x;
            tsq[j0] += p.x * p.x;
            tmax[j0 + 1] = fmaxf(tmax[j0 + 1], p.y);
            tmin[j0 + 1] = fminf(tmin[j0 + 1], p.y);
            tsum[j0 + 1] += p.y;
            tsq[j0 + 1] += p.y * p.y;
        }

    float* redA = &As[0][0];
    float* redB = &Bs[0][0];
    __syncthreads();
#pragma unroll
    for (int j = 0; j < 8; j++) {
        redA[ty * 132 + tx * 8 + j] = tmax[j];
        redB[ty * 132 + tx * 8 + j] = tmin[j];
    }
    __syncthreads();
    {
        int ct = tid >> 6;
        int base = (tid & 63) * 2;
        int bs0 = brow >> 5;
#pragma unroll
        for (int u = 0; u < 2; u++) {
            int col = base + u;
            float m = -1e30f, mn = 1e30f;
#pragma unroll
            for (int v = 0; v < 4; v++) {
                m = fmaxf(m, redA[(ct * 4 + v) * 132 + col]);
                mn = fminf(mn, redB[(ct * 4 + v) * 132 + col]);
            }
            size_t o = (size_t)(bs0 + ct) * CIN + bcol + col;
            g_pmax[o] = m;
            g_pmin[o] = mn;
        }
    }
    __syncthreads();
#pragma unroll
    for (int j = 0; j < 8; j++) {
        redA[ty * 132 + tx * 8 + j] = tsum[j];
        redB[ty * 132 + tx * 8 + j] = tsq[j];
    }
    __syncthreads();
    if (tid < 128) {
        float s = 0.f;
#pragma unroll
        for (int v = 0; v < 16; v++) s += redA[v * 132 + tid];
        atomicAdd(&g_sum[bcol + tid], s);
    } else {
        int col = tid - 128;
        float s = 0.f;
#pragma unroll
        for (int v = 0; v < 16; v++) s += redB[v * 132 + col];
        atomicAdd(&g_sumsq[bcol + col], s);
    }
}

// ---------------- gather-stats for y = G[nb] + C[center] ----------------
template <int CIN, int STAGE>
__global__ void stats_gather_k(int R) {
    const float* G = g_zbuf;
    const float* C = (STAGE == 0) ? g_c1out : g_c2out;
    const int* knn = (STAGE == 0) ? g_knn1 : g_knn2;
    constexpr int NPTS = (STAGE == 0) ? NN : S1V;
    constexpr int BSH = (STAGE == 0) ? 9 : 8;
    constexpr int NSEG = CIN / 128;

    int wid = (blockIdx.x * blockDim.x + threadIdx.x) >> 5;
    int lane = threadIdx.x & 31;
    int nw = (gridDim.x * blockDim.x) >> 5;
    float s[NSEG][4], q[NSEG][4];
#pragma unroll
    for (int sg = 0; sg < NSEG; sg++)
#pragma unroll
        for (int j = 0; j < 4; j++) { s[sg][j] = 0.f; q[sg][j] = 0.f; }

    for (int row = wid; row < R; row += nw) {
        int nb = knn[row];
        int bs = row >> 5;
        int b = bs >> BSH;
        size_t gb = ((size_t)(b * NPTS + nb)) * CIN;
        size_t cb = (size_t)bs * CIN;
#pragma unroll
        for (int sg = 0; sg < NSEG; sg++) {
            int col = sg * 128 + lane * 4;
            float4 g = *(const float4*)(G + gb + col);
            float4 c = *(const float4*)(C + cb + col);
            float y0 = g.x + c.x, y1 = g.y + c.y, y2 = g.z + c.z, y3 = g.w + c.w;
            s[sg][0] += y0; s[sg][1] += y1; s[sg][2] += y2; s[sg][3] += y3;
            q[sg][0] += y0 * y0; q[sg][1] += y1 * y1; q[sg][2] += y2 * y2; q[sg][3] += y3 * y3;
        }
    }
    __shared__ float ss[CIN], sq[CIN];
    for (int t = threadIdx.x; t < CIN; t += 256) { ss[t] = 0.f; sq[t] = 0.f; }
    __syncthreads();
#pragma unroll
    for (int sg = 0; sg < NSEG; sg++)
#pragma unroll
        for (int j = 0; j < 4; j++) {
            atomicAdd(&ss[sg * 128 + lane * 4 + j], s[sg][j]);
            atomicAdd(&sq[sg * 128 + lane * 4 + j], q[sg][j]);
        }
    __syncthreads();
    for (int t = threadIdx.x; t < CIN; t += 256) {
        atomicAdd(&g_sum[t], ss[t]);
        atomicAdd(&g_sumsq[t], sq[t]);
    }
}

// ---------------- weight diffs ----------------
__global__ void wdiff1_k(const float* __restrict__ w) {
    int i = blockIdx.x * 256 + threadIdx.x;
    int o = i >> 6, d = i & 63;
    g_wdiff1[i] = w[o * 128 + 64 + d] - w[o * 128 + d];
}
__global__ void wdiff2_k(const float* __restrict__ w) {
    int i = blockIdx.x * 256 + threadIdx.x;
    int o = i >> 7, d = i & 127;
    g_wdiff2[i] = w[o * 256 + 128 + d] - w[o * 256 + d];
}

// ---------------- center feature gathers ----------------
__global__ void gather_cfeat1() {
    int i = blockIdx.x * 256 + threadIdx.x;
    int r = i >> 6, c = i & 63;
    int b = r >> 9;
    int fid = g_fidx1[r];
    float v = g_f[((size_t)(b * NN + fid)) * 64 + c];
    g_cfeat1[i] = fmaxf(v * g_scale[c] + g_shift[c], 0.f);
}
__global__ void gather_cfeat2() {
    int i = blockIdx.x * 256 + threadIdx.x;
    int r = i >> 7, c = i & 127;
    int b = r >> 8;
    int fid = g_fidx2[r];
    g_cfeat2[i] = g_f1[((size_t)(b * S1V + fid)) * 128 + c];
}

// ---------------- pool finish ----------------
__global__ void pool_finish1() {
    int i = blockIdx.x * 256 + threadIdx.x;
    int c = i & 127;
    float sc = g_scale[c];
    float v = (sc >= 0.f) ? g_pmax[i] : g_pmin[i];
    g_f1[i] = fmaxf(sc * v + g_shift[c], 0.f);
}
__global__ void pool_finish2(float* __restrict__ out) {
    int i = blockIdx.x * 256 + threadIdx.x;
    int bs = i >> 8, o = i & 255;
    int b = bs >> 8, s = bs & 255;
    float sc = g_scale[o];
    float v = (sc >= 0.f) ? g_pmax[i] : g_pmin[i];
    out[((size_t)(b * 256 + o)) * 256 + s] = fmaxf(sc * v + g_shift[o], 0.f);
}

// ---------------- launch sequence (dual-stream DAG) ----------------
extern "C" void kernel_launch(void* const* d_in, const int* in_sizes, int n_in,
                              void* d_out, int out_size) {
    const float* x     = (const float*)d_in[0];
    const float* w1    = (const float*)d_in[1];
    const float* w2    = (const float*)d_in[2];
    const float* g1    = (const float*)d_in[3];
    const float* b1    = (const float*)d_in[4];
    const float* g2    = (const float*)d_in[5];
    const float* b2    = (const float*)d_in[6];
    const float* s1w1  = (const float*)d_in[7];
    const float* s1w2  = (const float*)d_in[8];
    const float* s1g1  = (const float*)d_in[9];
    const float* s1b1  = (const float*)d_in[10];
    const float* s1g2  = (const float*)d_in[11];
    const float* s1b2  = (const float*)d_in[12];
    const float* s2w1  = (const float*)d_in[13];
    const float* s2w2  = (const float*)d_in[14];
    const float* s2g1  = (const float*)d_in[15];
    const float* s2b1  = (const float*)d_in[16];
    const float* s2g2  = (const float*)d_in[17];
    const float* s2b2  = (const float*)d_in[18];
    float* out = (float*)d_out;

    const int RP = BB * NN;
    const int R1 = BB * S1V * KV;
    const int R2 = BB * S2V * KV;

    static cudaStream_t s2s = nullptr;
    static cudaEvent_t ev_prep = nullptr, ev_fps1 = nullptr, ev_knn1 = nullptr,
                       ev_fps2 = nullptr, ev_knn2 = nullptr;
    if (!s2s) {
        cudaStreamCreateWithFlags(&s2s, cudaStreamNonBlocking);
        cudaEventCreateWithFlags(&ev_prep, cudaEventDisableTiming);
        cudaEventCreateWithFlags(&ev_fps1, cudaEventDisableTiming);
        cudaEventCreateWithFlags(&ev_knn1, cudaEventDisableTiming);
        cudaEventCreateWithFlags(&ev_fps2, cudaEventDisableTiming);
        cudaEventCreateWithFlags(&ev_knn2, cudaEventDisableTiming);
    }
    cudaStream_t m = 0;

    // --- main: coords ---
    prep_coords<<<RP / 256, 256, 0, m>>>(x);
    cudaEventRecord(ev_prep, m);

    // --- side stream: sampling chain ---
    cudaStreamWaitEvent(s2s, ev_prep, 0);
    fps_kernel<NN, S1V, 1024, 10, 0><<<BB, 1024, 0, s2s>>>();
    cudaEventRecord(ev_fps1, s2s);
    gather_c2<<<BB * S1V / 256, 256, 0, s2s>>>();
    knn_kernel<NN, S1V, 0><<<BB * S1V / 4, 128, 0, s2s>>>();
    cudaEventRecord(ev_knn1, s2s);
    fps_kernel<S1V, S2V, 512, 9, 1><<<BB, 512, 0, s2s>>>();
    cudaEventRecord(ev_fps2, s2s);
    knn_kernel<S1V, S2V, 1><<<BB * S2V / 4, 128, 0, s2s>>>();
    cudaEventRecord(ev_knn2, s2s);

    // --- main: feature chain ---
    cbr1_kernel<<<512, 256, 0, m>>>(x, w1);
    finalize_stats<<<1, 256, 0, m>>>(g1, b1, 1.0f / RP, 64);
    cbr2_kernel<<<512, 256, 0, m>>>(w2);
    finalize_stats<<<1, 256, 0, m>>>(g2, b2, 1.0f / RP, 64);

    gemm_k<64, 128, true><<<dim3(512, 1), 256, 0, m>>>(2, s1w1, -1, 0, 128);
    wdiff1_k<<<128 * 64 / 256, 256, 0, m>>>(s1w1);
    cudaStreamWaitEvent(m, ev_fps1, 0);
    gather_cfeat1<<<BB * S1V * 64 / 256, 256, 0, m>>>();
    gemm_k<64, 64, false><<<dim3(64, 1), 256, 0, m>>>(3, nullptr, 7, 5, 128);

    cudaStreamWaitEvent(m, ev_knn1, 0);
    stats_gather_k<128, 0><<<512, 256, 0, m>>>(R1);
    finalize_stats<<<1, 256, 0, m>>>(s1g1, s1b1, 1.0f / R1, 128);

    gemm2_fused<128, 0><<<dim3(2048, 1), 256, 0, m>>>(s1w2);
    finalize_stats<<<1, 256, 0, m>>>(s1g2, s1b2, 1.0f / R1, 128);
    pool_finish1<<<BB * S1V * 128 / 256, 256, 0, m>>>();

    gemm_k<128, 256, false><<<dim3(64, 2), 256, 0, m>>>(9, s2w1, -1, 0, 256);
    wdiff2_k<<<256 * 128 / 256, 256, 0, m>>>(s2w1);
    cudaStreamWaitEvent(m, ev_fps2, 0);
    gather_cfeat2<<<BB * S2V * 128 / 256, 256, 0, m>>>();
    gemm_k<128, 128, false><<<dim3(32, 2), 256, 0, m>>>(4, nullptr, 8, 6, 256);

    cudaStreamWaitEvent(m, ev_knn2, 0);
    stats_gather_k<256, 1><<<512, 256, 0, m>>>(R2);
    finalize_stats<<<1, 256, 0, m>>>(s2g1, s2b1, 1.0f / R2, 256);

    gemm2_fused<256, 1><<<dim3(1024, 2), 256, 0, m>>>(s2w2);
    finalize_stats<<<1, 256, 0, m>>>(s2g2, s2b2, 1.0f / R2, 256);
    pool_finish2<<<BB * S2V * 256 / 256, 256, 0, m>>>(out);
}

// round 16
// speedup vs baseline: 1.3907x; 1.3907x over previous
#include <cuda_runtime.h>

#define BB 16
#define NN 4096
#define S1V 512
#define S2V 256
#define KV 32
#define EPSF 1e-5f

typedef unsigned long long ull;

// ---------------- f32x2 packed-FMA helpers ----------------
__device__ __forceinline__ void ffma2(ull& acc, ull a, ull b) {
    asm volatile("fma.rn.f32x2 %0, %1, %2, %0;" : "+l"(acc) : "l"(a), "l"(b));
}
__device__ __forceinline__ ull splat2(float x) {
    ull r;
    asm("mov.b64 %0, {%1, %1};" : "=l"(r) : "f"(x));
    return r;
}
__device__ __forceinline__ float2 unpk(ull v) {
    float lo, hi;
    asm("mov.b64 {%0, %1}, %2;" : "=f"(lo), "=f"(hi) : "l"(v));
    return make_float2(lo, hi);
}

// float -> order-preserving uint (handles negatives)
__device__ __forceinline__ unsigned fkey(float v) {
    unsigned u = __float_as_uint(v);
    return (u & 0x80000000u) ? ~u : (u | 0x80000000u);
}
__device__ __forceinline__ float funkey(unsigned k) {
    unsigned u = (k & 0x80000000u) ? (k ^ 0x80000000u) : ~k;
    return __uint_as_float(u);
}

// ---------------- scratch ----------------
__device__ __align__(16) float g_zbuf[33554432];
__device__ __align__(16) float g_f[BB * NN * 64];
__device__ __align__(16) float g_f1[BB * S1V * 128];
__device__ __align__(16) float g_cfeat1[BB * S1V * 64];
__device__ __align__(16) float g_cfeat2[BB * S2V * 128];
__device__ __align__(16) float g_c1out[BB * S1V * 128];
__device__ __align__(16) float g_c2out[BB * S2V * 256];
__device__ __align__(16) float g_wdiff1[128 * 64];
__device__ __align__(16) float g_wdiff2[256 * 128];
__device__ __align__(16) float g_pmax[1048576];
__device__ __align__(16) float g_pmin[1048576];
__device__ __align__(16) float4 g_pk1[BB * NN];     // (x,y,z,norm2)  for KNN
__device__ __align__(16) float4 g_pk2[BB * S1V];
__device__ float g_cx[BB * NN], g_cy[BB * NN], g_cz[BB * NN];       // SoA for FPS
__device__ float g_c2x[BB * S1V], g_c2y[BB * S1V], g_c2z[BB * S1V];
__device__ int   g_fidx1[BB * S1V], g_fidx2[BB * S2V];
__device__ int   g_knn1[BB * S1V * KV], g_knn2[BB * S2V * KV];
__device__ __align__(16) float g_sum[256], g_sumsq[256];
__device__ __align__(16) float g_scale[256], g_shift[256];

__device__ __forceinline__ float* buf_sel(int w) {
    switch (w) {
        case 0: return g_zbuf;
        case 2: return g_f;
        case 3: return g_cfeat1;
        case 4: return g_cfeat2;
        case 5: return g_c1out;
        case 6: return g_c2out;
        case 7: return g_wdiff1;
        case 8: return g_wdiff2;
        case 9: return g_f1;
    }
    return g_zbuf;
}

// ---------------- coords prep (SoA + packed) ----------------
__global__ void prep_coords(const float* __restrict__ x) {
    int i = blockIdx.x * 256 + threadIdx.x;
    int b = i >> 12, n = i & 4095;
    const float* xb = x + (size_t)b * 3 * NN;
    float X = xb[n], Y = xb[NN + n], Z = xb[2 * NN + n];
    g_cx[i] = X; g_cy[i] = Y; g_cz[i] = Z;
    g_pk1[i] = make_float4(X, Y, Z, X * X + Y * Y + Z * Z);
}

// ---------------- point_cbr stage 1 (fused stats) ----------------
__global__ void cbr1_kernel(const float* __restrict__ x, const float* __restrict__ w1) {
    __shared__ float ws[192];
    int tid = threadIdx.x;
    if (tid < 192) ws[tid] = w1[tid];
    __syncthreads();
    int o = tid & 63;
    float wa = ws[o * 3 + 0], wb = ws[o * 3 + 1], wc = ws[o * 3 + 2];
    float s = 0.f, q = 0.f;
    for (int i = blockIdx.x * 256 + tid; i < BB * NN * 64; i += 512 * 256) {
        int r = i >> 6;
        int b = r >> 12, n = r & 4095;
        const float* xb = x + (size_t)b * 3 * NN;
        float v = wa * xb[n] + wb * xb[NN + n] + wc * xb[2 * NN + n];
        g_zbuf[i] = v;
        s += v; q += v * v;
    }
    __shared__ float bs[256], bq[256];
    bs[tid] = s; bq[tid] = q;
    __syncthreads();
    if (tid < 64) {
        for (int j = tid + 64; j < 256; j += 64) { s += bs[j]; q += bq[j]; }
        atomicAdd(&g_sum[tid], s);
        atomicAdd(&g_sumsq[tid], q);
    }
}

// ---------------- point_cbr stage 2 (persistent blocks, fused stats) ----------------
__global__ void cbr2_kernel(const float* __restrict__ w2) {
    __shared__ float ys[4][64];
    __shared__ float wst[64 * 64];
    int tid = threadIdx.x;
    for (int j = tid; j < 4096; j += 256) {
        int o = j >> 6, c = j & 63;
        wst[c * 64 + o] = w2[j];
    }
    int rl = tid >> 6, o = tid & 63;
    float scl = g_scale[o], shf = g_shift[o];
    float s = 0.f, q = 0.f;
    for (int it = 0; it < 32; it++) {
        int r0 = (blockIdx.x * 32 + it) * 4;
        __syncthreads();
        {
            float v = g_zbuf[r0 * 64 + tid];
            v = fmaxf(v * scl + shf, 0.f);
            ((float*)ys)[tid] = v;
        }
        __syncthreads();
        float acc = 0.f;
#pragma unroll 16
        for (int c = 0; c < 64; c++) acc += ys[rl][c] * wst[c * 64 + o];
        g_f[(r0 + rl) * 64 + o] = acc;
        s += acc; q += acc * acc;
    }
    __shared__ float bs[256], bq[256];
    bs[tid] = s; bq[tid] = q;
    __syncthreads();
    if (tid < 64) {
        for (int j = tid + 64; j < 256; j += 64) { s += bs[j]; q += bq[j]; }
        atomicAdd(&g_sum[tid], s);
        atomicAdd(&g_sumsq[tid], q);
    }
}

// ---------------- finalize (zeroes accumulators for next use) ----------------
__global__ void finalize_stats(const float* __restrict__ g, const float* __restrict__ bias,
                               float invR, int O) {
    int o = threadIdx.x;   // 256
    float su = g_sum[o], sq = g_sumsq[o];
    g_sum[o] = 0.f; g_sumsq[o] = 0.f;
    if (o < O) {
        float m = su * invR;
        float v = sq * invR - m * m;
        float rstd = rsqrtf(v + EPSF);
        float sc = g[o] * rstd;
        g_scale[o] = sc;
        g_shift[o] = bias[o] - m * sc;
    }
}

// ---------------- FPS (R14 version: bit-exact, REDUX argmax, static reg indexing) ----
template <int NPTS, int NSAMP, int TPB, int STAGE>
__global__ void fps_kernel() {
    constexpr int PPT = NPTS / TPB;
    constexpr int NW = TPB / 32;
    const float* cx = (STAGE == 0) ? g_cx : g_c2x;
    const float* cy = (STAGE == 0) ? g_cy : g_c2y;
    const float* cz = (STAGE == 0) ? g_cz : g_c2z;
    int* fidx = (STAGE == 0) ? g_fidx1 : g_fidx2;
    int b = blockIdx.x, tid = threadIdx.x;
    const float* bx = cx + b * NPTS;
    const float* by = cy + b * NPTS;
    const float* bz = cz + b * NPTS;
    float px[PPT], py[PPT], pz[PPT], dist[PPT];
#pragma unroll
    for (int t = 0; t < PPT; t++) {
        int n = tid + t * TPB;
        px[t] = bx[n]; py[t] = by[n]; pz[t] = bz[n];
        dist[t] = 1e10f;
    }
    __shared__ unsigned wv[NW];
    __shared__ unsigned wi[NW];
    __shared__ int s_far;
    int far = 0;
    for (int s = 0; s < NSAMP; s++) {
        if (tid == 0) fidx[b * NSAMP + s] = far;
        float fx = bx[far], fy = by[far], fz = bz[far];
        float bv = -1.0f; int bi = 0x7fffffff;
#pragma unroll
        for (int t = 0; t < PPT; t++) {
            float dx = __fsub_rn(px[t], fx);
            float dy = __fsub_rn(py[t], fy);
            float dz = __fsub_rn(pz[t], fz);
            float d = __fadd_rn(__fadd_rn(__fmul_rn(dx, dx), __fmul_rn(dy, dy)), __fmul_rn(dz, dz));
            float nd = fminf(dist[t], d);
            dist[t] = nd;
            int n = tid + t * TPB;
            if (nd > bv) { bv = nd; bi = n; }   // lowest n on tie within thread
        }
        // warp argmax via REDUX (dist >= 0 so float bits are uint-monotonic)
        unsigned uv = __float_as_uint(bv);
        unsigned vmax = __reduce_max_sync(0xffffffffu, uv);
        unsigned cand = (uv == vmax) ? (unsigned)bi : 0xffffffffu;
        unsigned imin = __reduce_min_sync(0xffffffffu, cand);
        if ((tid & 31) == 0) { wv[tid >> 5] = vmax; wi[tid >> 5] = imin; }
        __syncthreads();
        if (tid < 32) {
            unsigned uv2 = (tid < NW) ? wv[tid] : 0u;
            unsigned i2 = (tid < NW) ? wi[tid] : 0xffffffffu;
            unsigned vm2 = __reduce_max_sync(0xffffffffu, uv2);
            unsigned c2 = (uv2 == vm2) ? i2 : 0xffffffffu;
            unsigned im2 = __reduce_min_sync(0xffffffffu, c2);
            if (tid == 0) s_far = (int)im2;
        }
        __syncthreads();
        far = s_far;
    }
}

// ---------------- gather sampled sg1 coords (SoA + packed) ----------------
__global__ void gather_c2() {
    int i = blockIdx.x * 256 + threadIdx.x;   // BB*S1V
    int b = i >> 9;
    int id = g_fidx1[i];
    float4 p = g_pk1[b * NN + id];
    g_c2x[i] = p.x; g_c2y[i] = p.y; g_c2z[i] = p.z;
    g_pk2[i] = p;
}

// ---------------- KNN: warp top-32, REDUX+ballot insertion, packed loads -------------
template <int NPTS, int S, int STAGE>
__global__ void knn_kernel() {
    const float4* pk = (STAGE == 0) ? g_pk1 : g_pk2;
    const int* fidx = (STAGE == 0) ? g_fidx1 : g_fidx2;
    int* knn = (STAGE == 0) ? g_knn1 : g_knn2;

    int gw = (blockIdx.x * blockDim.x + threadIdx.x) >> 5;
    int lane = threadIdx.x & 31;
    int b = gw / S;
    const float4* bp = pk + b * NPTS;
    int ci = fidx[gw];
    float4 f = bp[ci];
    float fx = f.x, fy = f.y, fz = f.z;

    // relative distance: d = ||p||^2 - 2<f,p>  (constant ||f||^2 dropped; order preserved)
    auto distf = [&](float4 p) {
        float dot = fmaf(fx, p.x, fmaf(fy, p.y, fz * p.z));
        return fmaf(-2.0f, dot, p.w);
    };

    float bd = distf(bp[lane]);
    int bidx = lane;

    float kv; int kl;
    auto rered = [&]() {
        unsigned k = fkey(bd);
        unsigned vmax = __reduce_max_sync(0xffffffffu, k);
        unsigned eq = __ballot_sync(0xffffffffu, k == vmax);
        kl = __ffs(eq) - 1;             // lowest lane holding the max
        kv = funkey(vmax);
    };
    rered();

    for (int base = 32; base < NPTS; base += 32) {
        float4 p = bp[base + lane];
        float d = distf(p);
        unsigned m = __ballot_sync(0xffffffffu, d < kv);
        while (m) {
            int src = __ffs(m) - 1;
            m &= m - 1;
            float dc = __shfl_sync(0xffffffffu, d, src);
            if (dc < kv) {
                if (lane == kl) { bd = dc; bidx = base + src; }
                rered();
            }
        }
    }
    knn[gw * KV + lane] = bidx;
}

// ---------------- smem swizzle ----------------
__device__ __forceinline__ int swz(int col) {
    int blk = col >> 5;
    return (blk << 5) + (((col & 31) + (blk << 2)) & 31);
}

// ---------------- plain swizzled double-buffered SGEMM (FFMA2 core) ----------------
template <int CIN, int WS, bool BNA>
__global__ __launch_bounds__(256) void gemm_k(int asel, const float* __restrict__ Wp_in,
                                              int wsel, int csel, int O) {
    const float* A = buf_sel(asel);
    const float* W = Wp_in ? Wp_in : buf_sel(wsel);
    float* C = buf_sel(csel);
    __shared__ float As[2][8 * 132];
    __shared__ float Bs[2][8 * 132];
    int tid = threadIdx.x;
    int brow = blockIdx.x * 128, bcol = blockIdx.y * 128;
    int tx = tid & 15, ty = tid >> 4;
    int lr = tid >> 1, lc = (tid & 1) * 4;
    const float* Ap = A + (size_t)(brow + lr) * CIN + lc;
    const float* Wp = W + (size_t)(bcol + lr) * WS + lc;
    int wp = swz(lr);
    int sa0 = swz(ty * 8), sa1 = swz(ty * 8 + 4);
    int sb0 = swz(tx * 8), sb1 = swz(tx * 8 + 4);

    float4 av = *(const float4*)Ap;
    float4 wv = *(const float4*)Wp;
    if (BNA) {
        float4 sc = *(const float4*)&g_scale[lc];
        float4 sh = *(const float4*)&g_shift[lc];
        av.x = fmaxf(av.x * sc.x + sh.x, 0.f);
        av.y = fmaxf(av.y * sc.y + sh.y, 0.f);
        av.z = fmaxf(av.z * sc.z + sh.z, 0.f);
        av.w = fmaxf(av.w * sc.w + sh.w, 0.f);
    }
    As[0][(lc + 0) * 132 + wp] = av.x; As[0][(lc + 1) * 132 + wp] = av.y;
    As[0][(lc + 2) * 132 + wp] = av.z; As[0][(lc + 3) * 132 + wp] = av.w;
    Bs[0][(lc + 0) * 132 + wp] = wv.x; Bs[0][(lc + 1) * 132 + wp] = wv.y;
    Bs[0][(lc + 2) * 132 + wp] = wv.z; Bs[0][(lc + 3) * 132 + wp] = wv.w;
    __syncthreads();

    ull acc2[8][4];
#pragma unroll
    for (int i = 0; i < 8; i++)
#pragma unroll
        for (int j = 0; j < 4; j++) acc2[i][j] = 0ull;

    constexpr int NIT = CIN / 8;
#pragma unroll 2
    for (int it = 0; it < NIT; it++) {
        int cur = it & 1;
        float4 av2, wv2;
        if (it + 1 < NIT) {
            av2 = *(const float4*)(Ap + (it + 1) * 8);
            wv2 = *(const float4*)(Wp + (it + 1) * 8);
            if (BNA) {
                float4 sc = *(const float4*)&g_scale[(it + 1) * 8 + lc];
                float4 sh = *(const float4*)&g_shift[(it + 1) * 8 + lc];
                av2.x = fmaxf(av2.x * sc.x + sh.x, 0.f);
                av2.y = fmaxf(av2.y * sc.y + sh.y, 0.f);
                av2.z = fmaxf(av2.z * sc.z + sh.z, 0.f);
                av2.w = fmaxf(av2.w * sc.w + sh.w, 0.f);
            }
        }
#pragma unroll
        for (int k = 0; k < 8; k++) {
            float4 a0 = *(const float4*)&As[cur][k * 132 + sa0];
            float4 a1 = *(const float4*)&As[cur][k * 132 + sa1];
            ulonglong2 bp0 = *(const ulonglong2*)&Bs[cur][k * 132 + sb0];
            ulonglong2 bp1 = *(const ulonglong2*)&Bs[cur][k * 132 + sb1];
            float a[8] = {a0.x, a0.y, a0.z, a0.w, a1.x, a1.y, a1.z, a1.w};
            ull bp[4] = {bp0.x, bp0.y, bp1.x, bp1.y};
#pragma unroll
            for (int i = 0; i < 8; i++) {
                ull as = splat2(a[i]);
#pragma unroll
                for (int j = 0; j < 4; j++) ffma2(acc2[i][j], as, bp[j]);
            }
        }
        if (it + 1 < NIT) {
            int nxt = 1 - cur;
            As[nxt][(lc + 0) * 132 + wp] = av2.x; As[nxt][(lc + 1) * 132 + wp] = av2.y;
            As[nxt][(lc + 2) * 132 + wp] = av2.z; As[nxt][(lc + 3) * 132 + wp] = av2.w;
            Bs[nxt][(lc + 0) * 132 + wp] = wv2.x; Bs[nxt][(lc + 1) * 132 + wp] = wv2.y;
            Bs[nxt][(lc + 2) * 132 + wp] = wv2.z; Bs[nxt][(lc + 3) * 132 + wp] = wv2.w;
            __syncthreads();
        }
    }
#pragma unroll
    for (int i = 0; i < 8; i++) {
        int r = brow + ty * 8 + i;
        float4* cp = (float4*)(C + (size_t)r * O + bcol + tx * 8);
        float2 p0 = unpk(acc2[i][0]), p1 = unpk(acc2[i][1]);
        float2 p2 = unpk(acc2[i][2]), p3 = unpk(acc2[i][3]);
        cp[0] = make_float4(p0.x, p0.y, p1.x, p1.y);
        cp[1] = make_float4(p2.x, p2.y, p3.x, p3.y);
    }
}

// ---------------- FUSED layer-2 GEMM (FFMA2 core) ----------------
template <int CIN, int STAGE>
__global__ __launch_bounds__(256) void gemm2_fused(const float* __restrict__ W) {
    const float* G = g_zbuf;
    const float* C = (STAGE == 0) ? g_c1out : g_c2out;
    const int* knn = (STAGE == 0) ? g_knn1 : g_knn2;
    constexpr int NPTS = (STAGE == 0) ? NN : S1V;
    constexpr int BSH = (STAGE == 0) ? 9 : 8;

    __shared__ float As[2][8 * 132];
    __shared__ float Bs[2][8 * 132];
    int tid = threadIdx.x;
    int brow = blockIdx.x * 128, bcol = blockIdx.y * 128;
    int tx = tid & 15, ty = tid >> 4;
    int lr = tid >> 1, lc = (tid & 1) * 4;

    int grow = brow + lr;
    int nb = knn[grow];
    int bs = grow >> 5;
    int b = bs >> BSH;
    const float* Gp = G + ((size_t)(b * NPTS + nb)) * CIN + lc;
    const float* Cp = C + (size_t)bs * CIN + lc;
    const float* Wp = W + (size_t)(bcol + lr) * CIN + lc;
    int wp = swz(lr);
    int sa0 = swz(ty * 8), sa1 = swz(ty * 8 + 4);
    int sb0 = swz(tx * 8), sb1 = swz(tx * 8 + 4);

    {
        float4 gv = *(const float4*)Gp;
        float4 cv = *(const float4*)Cp;
        float4 wv = *(const float4*)Wp;
        float4 sc = *(const float4*)&g_scale[lc];
        float4 sh = *(const float4*)&g_shift[lc];
        float ax = fmaxf((gv.x + cv.x) * sc.x + sh.x, 0.f);
        float ay = fmaxf((gv.y + cv.y) * sc.y + sh.y, 0.f);
        float az = fmaxf((gv.z + cv.z) * sc.z + sh.z, 0.f);
        float aw = fmaxf((gv.w + cv.w) * sc.w + sh.w, 0.f);
        As[0][(lc + 0) * 132 + wp] = ax; As[0][(lc + 1) * 132 + wp] = ay;
        As[0][(lc + 2) * 132 + wp] = az; As[0][(lc + 3) * 132 + wp] = aw;
        Bs[0][(lc + 0) * 132 + wp] = wv.x; Bs[0][(lc + 1) * 132 + wp] = wv.y;
        Bs[0][(lc + 2) * 132 + wp] = wv.z; Bs[0][(lc + 3) * 132 + wp] = wv.w;
    }
    __syncthreads();

    ull acc2[8][4];
#pragma unroll
    for (int i = 0; i < 8; i++)
#pragma unroll
        for (int j = 0; j < 4; j++) acc2[i][j] = 0ull;

    constexpr int NIT = CIN / 8;
#pragma unroll 2
    for (int it = 0; it < NIT; it++) {
        int cur = it & 1;
        float axp, ayp, azp, awp;
        float4 wv2;
        if (it + 1 < NIT) {
            float4 gv = *(const float4*)(Gp + (it + 1) * 8);
            float4 cv = *(const float4*)(Cp + (it + 1) * 8);
            wv2 = *(const float4*)(Wp + (it + 1) * 8);
            float4 sc = *(const float4*)&g_scale[(it + 1) * 8 + lc];
            float4 sh = *(const float4*)&g_shift[(it + 1) * 8 + lc];
            axp = fmaxf((gv.x + cv.x) * sc.x + sh.x, 0.f);
            ayp = fmaxf((gv.y + cv.y) * sc.y + sh.y, 0.f);
            azp = fmaxf((gv.z + cv.z) * sc.z + sh.z, 0.f);
            awp = fmaxf((gv.w + cv.w) * sc.w + sh.w, 0.f);
        }
#pragma unroll
        for (int k = 0; k < 8; k++) {
            float4 a0 = *(const float4*)&As[cur][k * 132 + sa0];
            float4 a1 = *(const float4*)&As[cur][k * 132 + sa1];
            ulonglong2 bp0 = *(const ulonglong2*)&Bs[cur][k * 132 + sb0];
            ulonglong2 bp1 = *(const ulonglong2*)&Bs[cur][k * 132 + sb1];
            float a[8] = {a0.x, a0.y, a0.z, a0.w, a1.x, a1.y, a1.z, a1.w};
            ull bp[4] = {bp0.x, bp0.y, bp1.x, bp1.y};
#pragma unroll
            for (int i = 0; i < 8; i++) {
                ull as = splat2(a[i]);
#pragma unroll
                for (int j = 0; j < 4; j++) ffma2(acc2[i][j], as, bp[j]);
            }
        }
        if (it + 1 < NIT) {
            int nxt = 1 - cur;
            As[nxt][(lc + 0) * 132 + wp] = axp; As[nxt][(lc + 1) * 132 + wp] = ayp;
            As[nxt][(lc + 2) * 132 + wp] = azp; As[nxt][(lc + 3) * 132 + wp] = awp;
            Bs[nxt][(lc + 0) * 132 + wp] = wv2.x; Bs[nxt][(lc + 1) * 132 + wp] = wv2.y;
            Bs[nxt][(lc + 2) * 132 + wp] = wv2.z; Bs[nxt][(lc + 3) * 132 + wp] = wv2.w;
            __syncthreads();
        }
    }

    float tmax[8], tmin[8], tsum[8], tsq[8];
#pragma unroll
    for (int j = 0; j < 8; j++) { tmax[j] = -1e30f; tmin[j] = 1e30f; tsum[j] = 0.f; tsq[j] = 0.f; }
#pragma unroll
    for (int i = 0; i < 8; i++)
#pragma unroll
        for (int jp = 0; jp < 4; jp++) {
            float2 p = unpk(acc2[i][jp]);
            int j0 = jp * 2;
            tmax[j0] = fmaxf(tmax[j0], p.x);
            tmin[j0] = fminf(tmin[j0], p.x);
            tsum[j0] += p.x;
            tsq[j0] += p.x * p.x;
            tmax[j0 + 1] = fmaxf(tmax[j0 + 1], p.y);
            tmin[j0 + 1] = fminf(tmin[j0 + 1], p.y);
            tsum[j0 + 1] += p.y;
            tsq[j0 + 1] += p.y * p.y;
        }

    float* redA = &As[0][0];
    float* redB = &Bs[0][0];
    __syncthreads();
#pragma unroll
    for (int j = 0; j < 8; j++) {
        redA[ty * 132 + tx * 8 + j] = tmax[j];
        redB[ty * 132 + tx * 8 + j] = tmin[j];
    }
    __syncthreads();
    {
        int ct = tid >> 6;
        int base = (tid & 63) * 2;
        int bs0 = brow >> 5;
#pragma unroll
        for (int u = 0; u < 2; u++) {
            int col = base + u;
            float m = -1e30f, mn = 1e30f;
#pragma unroll
            for (int v = 0; v < 4; v++) {
                m = fmaxf(m, redA[(ct * 4 + v) * 132 + col]);
                mn = fminf(mn, redB[(ct * 4 + v) * 132 + col]);
            }
            size_t o = (size_t)(bs0 + ct) * CIN + bcol + col;
            g_pmax[o] = m;
            g_pmin[o] = mn;
        }
    }
    __syncthreads();
#pragma unroll
    for (int j = 0; j < 8; j++) {
        redA[ty * 132 + tx * 8 + j] = tsum[j];
        redB[ty * 132 + tx * 8 + j] = tsq[j];
    }
    __syncthreads();
    if (tid < 128) {
        float s = 0.f;
#pragma unroll
        for (int v = 0; v < 16; v++) s += redA[v * 132 + tid];
        atomicAdd(&g_sum[bcol + tid], s);
    } else {
        int col = tid - 128;
        float s = 0.f;
#pragma unroll
        for (int v = 0; v < 16; v++) s += redB[v * 132 + col];
        atomicAdd(&g_sumsq[bcol + col], s);
    }
}

// ---------------- gather-stats for y = G[nb] + C[center] ----------------
template <int CIN, int STAGE>
__global__ void stats_gather_k(int R) {
    const float* G = g_zbuf;
    const float* C = (STAGE == 0) ? g_c1out : g_c2out;
    const int* knn = (STAGE == 0) ? g_knn1 : g_knn2;
    constexpr int NPTS = (STAGE == 0) ? NN : S1V;
    constexpr int BSH = (STAGE == 0) ? 9 : 8;
    constexpr int NSEG = CIN / 128;

    int wid = (blockIdx.x * blockDim.x + threadIdx.x) >> 5;
    int lane = threadIdx.x & 31;
    int nw = (gridDim.x * blockDim.x) >> 5;
    float s[NSEG][4], q[NSEG][4];
#pragma unroll
    for (int sg = 0; sg < NSEG; sg++)
#pragma unroll
        for (int j = 0; j < 4; j++) { s[sg][j] = 0.f; q[sg][j] = 0.f; }

    for (int row = wid; row < R; row += nw) {
        int nb = knn[row];
        int bs = row >> 5;
        int b = bs >> BSH;
        size_t gb = ((size_t)(b * NPTS + nb)) * CIN;
        size_t cb = (size_t)bs * CIN;
#pragma unroll
        for (int sg = 0; sg < NSEG; sg++) {
            int col = sg * 128 + lane * 4;
            float4 g = *(const float4*)(G + gb + col);
            float4 c = *(const float4*)(C + cb + col);
            float y0 = g.x + c.x, y1 = g.y + c.y, y2 = g.z + c.z, y3 = g.w + c.w;
            s[sg][0] += y0; s[sg][1] += y1; s[sg][2] += y2; s[sg][3] += y3;
            q[sg][0] += y0 * y0; q[sg][1] += y1 * y1; q[sg][2] += y2 * y2; q[sg][3] += y3 * y3;
        }
    }
    __shared__ float ss[CIN], sq[CIN];
    for (int t = threadIdx.x; t < CIN; t += 256) { ss[t] = 0.f; sq[t] = 0.f; }
    __syncthreads();
#pragma unroll
    for (int sg = 0; sg < NSEG; sg++)
#pragma unroll
        for (int j = 0; j < 4; j++) {
            atomicAdd(&ss[sg * 128 + lane * 4 + j], s[sg][j]);
            atomicAdd(&sq[sg * 128 + lane * 4 + j], q[sg][j]);
        }
    __syncthreads();
    for (int t = threadIdx.x; t < CIN; t += 256) {
        atomicAdd(&g_sum[t], ss[t]);
        atomicAdd(&g_sumsq[t], sq[t]);
    }
}

// ---------------- weight diffs ----------------
__global__ void wdiff1_k(const float* __restrict__ w) {
    int i = blockIdx.x * 256 + threadIdx.x;
    int o = i >> 6, d = i & 63;
    g_wdiff1[i] = w[o * 128 + 64 + d] - w[o * 128 + d];
}
__global__ void wdiff2_k(const float* __restrict__ w) {
    int i = blockIdx.x * 256 + threadIdx.x;
    int o = i >> 7, d = i & 127;
    g_wdiff2[i] = w[o * 256 + 128 + d] - w[o * 256 + d];
}

// ---------------- center feature gathers ----------------
__global__ void gather_cfeat1() {
    int i = blockIdx.x * 256 + threadIdx.x;
    int r = i >> 6, c = i & 63;
    int b = r >> 9;
    int fid = g_fidx1[r];
    float v = g_f[((size_t)(b * NN + fid)) * 64 + c];
    g_cfeat1[i] = fmaxf(v * g_scale[c] + g_shift[c], 0.f);
}
__global__ void gather_cfeat2() {
    int i = blockIdx.x * 256 + threadIdx.x;
    int r = i >> 7, c = i & 127;
    int b = r >> 8;
    int fid = g_fidx2[r];
    g_cfeat2[i] = g_f1[((size_t)(b * S1V + fid)) * 128 + c];
}

// ---------------- pool finish ----------------
__global__ void pool_finish1() {
    int i = blockIdx.x * 256 + threadIdx.x;
    int c = i & 127;
    float sc = g_scale[c];
    float v = (sc >= 0.f) ? g_pmax[i] : g_pmin[i];
    g_f1[i] = fmaxf(sc * v + g_shift[c], 0.f);
}
__global__ void pool_finish2(float* __restrict__ out) {
    int i = blockIdx.x * 256 + threadIdx.x;
    int bs = i >> 8, o = i & 255;
    int b = bs >> 8, s = bs & 255;
    float sc = g_scale[o];
    float v = (sc >= 0.f) ? g_pmax[i] : g_pmin[i];
    out[((size_t)(b * 256 + o)) * 256 + s] = fmaxf(sc * v + g_shift[o], 0.f);
}

// ---------------- launch sequence (triple-stream DAG) ----------------
extern "C" void kernel_launch(void* const* d_in, const int* in_sizes, int n_in,
                              void* d_out, int out_size) {
    const float* x     = (const float*)d_in[0];
    const float* w1    = (const float*)d_in[1];
    const float* w2    = (const float*)d_in[2];
    const float* g1    = (const float*)d_in[3];
    const float* b1    = (const float*)d_in[4];
    const float* g2    = (const float*)d_in[5];
    const float* b2    = (const float*)d_in[6];
    const float* s1w1  = (const float*)d_in[7];
    const float* s1w2  = (const float*)d_in[8];
    const float* s1g1  = (const float*)d_in[9];
    const float* s1b1  = (const float*)d_in[10];
    const float* s1g2  = (const float*)d_in[11];
    const float* s1b2  = (const float*)d_in[12];
    const float* s2w1  = (const float*)d_in[13];
    const float* s2w2  = (const float*)d_in[14];
    const float* s2g1  = (const float*)d_in[15];
    const float* s2b1  = (const float*)d_in[16];
    const float* s2g2  = (const float*)d_in[17];
    const float* s2b2  = (const float*)d_in[18];
    float* out = (float*)d_out;

    const int RP = BB * NN;
    const int R1 = BB * S1V * KV;
    const int R2 = BB * S2V * KV;

    static cudaStream_t sA = nullptr, sB = nullptr;
    static cudaEvent_t ev_prep = nullptr, ev_fps1 = nullptr, ev_gc2 = nullptr,
                       ev_knn1 = nullptr, ev_fps2 = nullptr, ev_knn2 = nullptr;
    if (!sA) {
        cudaStreamCreateWithFlags(&sA, cudaStreamNonBlocking);
        cudaStreamCreateWithFlags(&sB, cudaStreamNonBlocking);
        cudaEventCreateWithFlags(&ev_prep, cudaEventDisableTiming);
        cudaEventCreateWithFlags(&ev_fps1, cudaEventDisableTiming);
        cudaEventCreateWithFlags(&ev_gc2, cudaEventDisableTiming);
        cudaEventCreateWithFlags(&ev_knn1, cudaEventDisableTiming);
        cudaEventCreateWithFlags(&ev_fps2, cudaEventDisableTiming);
        cudaEventCreateWithFlags(&ev_knn2, cudaEventDisableTiming);
    }
    cudaStream_t m = 0;

    // --- main: coords ---
    prep_coords<<<RP / 256, 256, 0, m>>>(x);
    cudaEventRecord(ev_prep, m);

    // --- stream A: fps1 -> gather_c2 -> knn1 ---
    cudaStreamWaitEvent(sA, ev_prep, 0);
    fps_kernel<NN, S1V, 1024, 0><<<BB, 1024, 0, sA>>>();
    cudaEventRecord(ev_fps1, sA);
    gather_c2<<<BB * S1V / 256, 256, 0, sA>>>();
    cudaEventRecord(ev_gc2, sA);
    knn_kernel<NN, S1V, 0><<<BB * S1V / 4, 128, 0, sA>>>();
    cudaEventRecord(ev_knn1, sA);

    // --- stream B: fps2 -> knn2 (concurrent with knn1) ---
    cudaStreamWaitEvent(sB, ev_gc2, 0);
    fps_kernel<S1V, S2V, 512, 1><<<BB, 512, 0, sB>>>();
    cudaEventRecord(ev_fps2, sB);
    knn_kernel<S1V, S2V, 1><<<BB * S2V / 4, 128, 0, sB>>>();
    cudaEventRecord(ev_knn2, sB);

    // --- main: feature chain ---
    cbr1_kernel<<<512, 256, 0, m>>>(x, w1);
    finalize_stats<<<1, 256, 0, m>>>(g1, b1, 1.0f / RP, 64);
    cbr2_kernel<<<512, 256, 0, m>>>(w2);
    finalize_stats<<<1, 256, 0, m>>>(g2, b2, 1.0f / RP, 64);

    gemm_k<64, 128, true><<<dim3(512, 1), 256, 0, m>>>(2, s1w1, -1, 0, 128);
    wdiff1_k<<<128 * 64 / 256, 256, 0, m>>>(s1w1);
    cudaStreamWaitEvent(m, ev_fps1, 0);
    gather_cfeat1<<<BB * S1V * 64 / 256, 256, 0, m>>>();
    gemm_k<64, 64, false><<<dim3(64, 1), 256, 0, m>>>(3, nullptr, 7, 5, 128);

    cudaStreamWaitEvent(m, ev_knn1, 0);
    stats_gather_k<128, 0><<<512, 256, 0, m>>>(R1);
    finalize_stats<<<1, 256, 0, m>>>(s1g1, s1b1, 1.0f / R1, 128);

    gemm2_fused<128, 0><<<dim3(2048, 1), 256, 0, m>>>(s1w2);
    finalize_stats<<<1, 256, 0, m>>>(s1g2, s1b2, 1.0f / R1, 128);
    pool_finish1<<<BB * S1V * 128 / 256, 256, 0, m>>>();

    gemm_k<128, 256, false><<<dim3(64, 2), 256, 0, m>>>(9, s2w1, -1, 0, 256);
    wdiff2_k<<<256 * 128 / 256, 256, 0, m>>>(s2w1);
    cudaStreamWaitEvent(m, ev_fps2, 0);
    gather_cfeat2<<<BB * S2V * 128 / 256, 256, 0, m>>>();
    gemm_k<128, 128, false><<<dim3(32, 2), 256, 0, m>>>(4, nullptr, 8, 6, 256);

    cudaStreamWaitEvent(m, ev_knn2, 0);
    stats_gather_k<256, 1><<<512, 256, 0, m>>>(R2);
    finalize_stats<<<1, 256, 0, m>>>(s2g1, s2b1, 1.0f / R2, 256);

    gemm2_fused<256, 1><<<dim3(1024, 2), 256, 0, m>>>(s2w2);
    finalize_stats<<<1, 256, 0, m>>>(s2g2, s2b2, 1.0f / R2, 256);
    pool_finish2<<<BB * S2V * 256 / 256, 256, 0, m>>>(out);
}

// round 17
// speedup vs baseline: 1.8879x; 1.3576x over previous
#include <cuda_runtime.h>

#define BB 16
#define NN 4096
#define S1V 512
#define S2V 256
#define KV 32
#define EPSF 1e-5f

typedef unsigned long long ull;
typedef unsigned int uint;

// ---------------- f32x2 packed-FMA helpers ----------------
__device__ __forceinline__ void ffma2(ull& acc, ull a, ull b) {
    asm volatile("fma.rn.f32x2 %0, %1, %2, %0;" : "+l"(acc) : "l"(a), "l"(b));
}
__device__ __forceinline__ ull splat2(float x) {
    ull r;
    asm("mov.b64 %0, {%1, %1};" : "=l"(r) : "f"(x));
    return r;
}
__device__ __forceinline__ float2 unpk(ull v) {
    float lo, hi;
    asm("mov.b64 {%0, %1}, %2;" : "=f"(lo), "=f"(hi) : "l"(v));
    return make_float2(lo, hi);
}

// float -> order-preserving uint (handles negatives)
__device__ __forceinline__ unsigned fkey(float v) {
    unsigned u = __float_as_uint(v);
    return (u & 0x80000000u) ? ~u : (u | 0x80000000u);
}
__device__ __forceinline__ float funkey(unsigned k) {
    unsigned u = (k & 0x80000000u) ? (k ^ 0x80000000u) : ~k;
    return __uint_as_float(u);
}

// fp32 -> tf32 bits
__device__ __forceinline__ uint totf32(float x) {
    uint r;
    asm("cvt.rna.tf32.f32 %0, %1;" : "=r"(r) : "f"(x));
    return r;
}

// ---------------- scratch ----------------
__device__ __align__(16) float g_zbuf[33554432];
__device__ __align__(16) float g_f[BB * NN * 64];
__device__ __align__(16) float g_f1[BB * S1V * 128];
__device__ __align__(16) float g_cfeat1[BB * S1V * 64];
__device__ __align__(16) float g_cfeat2[BB * S2V * 128];
__device__ __align__(16) float g_c1out[BB * S1V * 128];
__device__ __align__(16) float g_c2out[BB * S2V * 256];
__device__ __align__(16) float g_wdiff1[128 * 64];
__device__ __align__(16) float g_wdiff2[256 * 128];
__device__ __align__(16) float g_pmax[1048576];
__device__ __align__(16) float g_pmin[1048576];
__device__ __align__(16) float4 g_pk1[BB * NN];     // (x,y,z,norm2)  for KNN
__device__ __align__(16) float4 g_pk2[BB * S1V];
__device__ float g_cx[BB * NN], g_cy[BB * NN], g_cz[BB * NN];       // SoA for FPS
__device__ float g_c2x[BB * S1V], g_c2y[BB * S1V], g_c2z[BB * S1V];
__device__ int   g_fidx1[BB * S1V], g_fidx2[BB * S2V];
__device__ int   g_knn1[BB * S1V * KV], g_knn2[BB * S2V * KV];
__device__ __align__(16) float g_sum[256], g_sumsq[256];
__device__ __align__(16) float g_scale[256], g_shift[256];

__device__ __forceinline__ float* buf_sel(int w) {
    switch (w) {
        case 0: return g_zbuf;
        case 2: return g_f;
        case 3: return g_cfeat1;
        case 4: return g_cfeat2;
        case 5: return g_c1out;
        case 6: return g_c2out;
        case 7: return g_wdiff1;
        case 8: return g_wdiff2;
        case 9: return g_f1;
    }
    return g_zbuf;
}

// ---------------- coords prep (SoA + packed) ----------------
__global__ void prep_coords(const float* __restrict__ x) {
    int i = blockIdx.x * 256 + threadIdx.x;
    int b = i >> 12, n = i & 4095;
    const float* xb = x + (size_t)b * 3 * NN;
    float X = xb[n], Y = xb[NN + n], Z = xb[2 * NN + n];
    g_cx[i] = X; g_cy[i] = Y; g_cz[i] = Z;
    g_pk1[i] = make_float4(X, Y, Z, X * X + Y * Y + Z * Z);
}

// ---------------- point_cbr stage 1 (fused stats) ----------------
__global__ void cbr1_kernel(const float* __restrict__ x, const float* __restrict__ w1) {
    __shared__ float ws[192];
    int tid = threadIdx.x;
    if (tid < 192) ws[tid] = w1[tid];
    __syncthreads();
    int o = tid & 63;
    float wa = ws[o * 3 + 0], wb = ws[o * 3 + 1], wc = ws[o * 3 + 2];
    float s = 0.f, q = 0.f;
    for (int i = blockIdx.x * 256 + tid; i < BB * NN * 64; i += 512 * 256) {
        int r = i >> 6;
        int b = r >> 12, n = r & 4095;
        const float* xb = x + (size_t)b * 3 * NN;
        float v = wa * xb[n] + wb * xb[NN + n] + wc * xb[2 * NN + n];
        g_zbuf[i] = v;
        s += v; q += v * v;
    }
    __shared__ float bs[256], bq[256];
    bs[tid] = s; bq[tid] = q;
    __syncthreads();
    if (tid < 64) {
        for (int j = tid + 64; j < 256; j += 64) { s += bs[j]; q += bq[j]; }
        atomicAdd(&g_sum[tid], s);
        atomicAdd(&g_sumsq[tid], q);
    }
}

// ---------------- point_cbr stage 2 (persistent blocks, fused stats) ----------------
__global__ void cbr2_kernel(const float* __restrict__ w2) {
    __shared__ float ys[4][64];
    __shared__ float wst[64 * 64];
    int tid = threadIdx.x;
    for (int j = tid; j < 4096; j += 256) {
        int o = j >> 6, c = j & 63;
        wst[c * 64 + o] = w2[j];
    }
    int rl = tid >> 6, o = tid & 63;
    float scl = g_scale[o], shf = g_shift[o];
    float s = 0.f, q = 0.f;
    for (int it = 0; it < 32; it++) {
        int r0 = (blockIdx.x * 32 + it) * 4;
        __syncthreads();
        {
            float v = g_zbuf[r0 * 64 + tid];
            v = fmaxf(v * scl + shf, 0.f);
            ((float*)ys)[tid] = v;
        }
        __syncthreads();
        float acc = 0.f;
#pragma unroll 16
        for (int c = 0; c < 64; c++) acc += ys[rl][c] * wst[c * 64 + o];
        g_f[(r0 + rl) * 64 + o] = acc;
        s += acc; q += acc * acc;
    }
    __shared__ float bs[256], bq[256];
    bs[tid] = s; bq[tid] = q;
    __syncthreads();
    if (tid < 64) {
        for (int j = tid + 64; j < 256; j += 64) { s += bs[j]; q += bq[j]; }
        atomicAdd(&g_sum[tid], s);
        atomicAdd(&g_sumsq[tid], q);
    }
}

// ---------------- finalize (zeroes accumulators for next use) ----------------
__global__ void finalize_stats(const float* __restrict__ g, const float* __restrict__ bias,
                               float invR, int O) {
    int o = threadIdx.x;   // 256
    float su = g_sum[o], sq = g_sumsq[o];
    g_sum[o] = 0.f; g_sumsq[o] = 0.f;
    if (o < O) {
        float m = su * invR;
        float v = sq * invR - m * m;
        float rstd = rsqrtf(v + EPSF);
        float sc = g[o] * rstd;
        g_scale[o] = sc;
        g_shift[o] = bias[o] - m * sc;
    }
}

// ---------------- FPS (bit-exact, REDUX argmax, static reg indexing) ----------------
template <int NPTS, int NSAMP, int TPB, int STAGE>
__global__ void fps_kernel() {
    constexpr int PPT = NPTS / TPB;
    constexpr int NW = TPB / 32;
    const float* cx = (STAGE == 0) ? g_cx : g_c2x;
    const float* cy = (STAGE == 0) ? g_cy : g_c2y;
    const float* cz = (STAGE == 0) ? g_cz : g_c2z;
    int* fidx = (STAGE == 0) ? g_fidx1 : g_fidx2;
    int b = blockIdx.x, tid = threadIdx.x;
    const float* bx = cx + b * NPTS;
    const float* by = cy + b * NPTS;
    const float* bz = cz + b * NPTS;
    float px[PPT], py[PPT], pz[PPT], dist[PPT];
#pragma unroll
    for (int t = 0; t < PPT; t++) {
        int n = tid + t * TPB;
        px[t] = bx[n]; py[t] = by[n]; pz[t] = bz[n];
        dist[t] = 1e10f;
    }
    __shared__ unsigned wv[NW];
    __shared__ unsigned wi[NW];
    __shared__ int s_far;
    int far = 0;
    for (int s = 0; s < NSAMP; s++) {
        if (tid == 0) fidx[b * NSAMP + s] = far;
        float fx = bx[far], fy = by[far], fz = bz[far];
        float bv = -1.0f; int bi = 0x7fffffff;
#pragma unroll
        for (int t = 0; t < PPT; t++) {
            float dx = __fsub_rn(px[t], fx);
            float dy = __fsub_rn(py[t], fy);
            float dz = __fsub_rn(pz[t], fz);
            float d = __fadd_rn(__fadd_rn(__fmul_rn(dx, dx), __fmul_rn(dy, dy)), __fmul_rn(dz, dz));
            float nd = fminf(dist[t], d);
            dist[t] = nd;
            int n = tid + t * TPB;
            if (nd > bv) { bv = nd; bi = n; }
        }
        unsigned uv = __float_as_uint(bv);
        unsigned vmax = __reduce_max_sync(0xffffffffu, uv);
        unsigned cand = (uv == vmax) ? (unsigned)bi : 0xffffffffu;
        unsigned imin = __reduce_min_sync(0xffffffffu, cand);
        if ((tid & 31) == 0) { wv[tid >> 5] = vmax; wi[tid >> 5] = imin; }
        __syncthreads();
        if (tid < 32) {
            unsigned uv2 = (tid < NW) ? wv[tid] : 0u;
            unsigned i2 = (tid < NW) ? wi[tid] : 0xffffffffu;
            unsigned vm2 = __reduce_max_sync(0xffffffffu, uv2);
            unsigned c2 = (uv2 == vm2) ? i2 : 0xffffffffu;
            unsigned im2 = __reduce_min_sync(0xffffffffu, c2);
            if (tid == 0) s_far = (int)im2;
        }
        __syncthreads();
        far = s_far;
    }
}

// ---------------- gather sampled sg1 coords (SoA + packed) ----------------
__global__ void gather_c2() {
    int i = blockIdx.x * 256 + threadIdx.x;   // BB*S1V
    int b = i >> 9;
    int id = g_fidx1[i];
    float4 p = g_pk1[b * NN + id];
    g_c2x[i] = p.x; g_c2y[i] = p.y; g_c2z[i] = p.z;
    g_pk2[i] = p;
}

// ---------------- KNN: warp top-32, REDUX+ballot insertion, packed loads -------------
template <int NPTS, int S, int STAGE>
__global__ void knn_kernel() {
    const float4* pk = (STAGE == 0) ? g_pk1 : g_pk2;
    const int* fidx = (STAGE == 0) ? g_fidx1 : g_fidx2;
    int* knn = (STAGE == 0) ? g_knn1 : g_knn2;

    int gw = (blockIdx.x * blockDim.x + threadIdx.x) >> 5;
    int lane = threadIdx.x & 31;
    int b = gw / S;
    const float4* bp = pk + b * NPTS;
    int ci = fidx[gw];
    float4 f = bp[ci];
    float fx = f.x, fy = f.y, fz = f.z;

    auto distf = [&](float4 p) {
        float dot = fmaf(fx, p.x, fmaf(fy, p.y, fz * p.z));
        return fmaf(-2.0f, dot, p.w);
    };

    float bd = distf(bp[lane]);
    int bidx = lane;

    float kv; int kl;
    auto rered = [&]() {
        unsigned k = fkey(bd);
        unsigned vmax = __reduce_max_sync(0xffffffffu, k);
        unsigned eq = __ballot_sync(0xffffffffu, k == vmax);
        kl = __ffs(eq) - 1;
        kv = funkey(vmax);
    };
    rered();

    for (int base = 32; base < NPTS; base += 32) {
        float4 p = bp[base + lane];
        float d = distf(p);
        unsigned m = __ballot_sync(0xffffffffu, d < kv);
        while (m) {
            int src = __ffs(m) - 1;
            m &= m - 1;
            float dc = __shfl_sync(0xffffffffu, d, src);
            if (dc < kv) {
                if (lane == kl) { bd = dc; bidx = base + src; }
                rered();
            }
        }
    }
    knn[gw * KV + lane] = bidx;
}

// ---------------- smem swizzle (for FFMA2 gemm) ----------------
__device__ __forceinline__ int swz(int col) {
    int blk = col >> 5;
    return (blk << 5) + (((col & 31) + (blk << 2)) & 31);
}

// ---------------- plain swizzled double-buffered SGEMM (FFMA2 core) ----------------
template <int CIN, int WS, bool BNA>
__global__ __launch_bounds__(256) void gemm_k(int asel, const float* __restrict__ Wp_in,
                                              int wsel, int csel, int O) {
    const float* A = buf_sel(asel);
    const float* W = Wp_in ? Wp_in : buf_sel(wsel);
    float* C = buf_sel(csel);
    __shared__ float As[2][8 * 132];
    __shared__ float Bs[2][8 * 132];
    int tid = threadIdx.x;
    int brow = blockIdx.x * 128, bcol = blockIdx.y * 128;
    int tx = tid & 15, ty = tid >> 4;
    int lr = tid >> 1, lc = (tid & 1) * 4;
    const float* Ap = A + (size_t)(brow + lr) * CIN + lc;
    const float* Wp = W + (size_t)(bcol + lr) * WS + lc;
    int wp = swz(lr);
    int sa0 = swz(ty * 8), sa1 = swz(ty * 8 + 4);
    int sb0 = swz(tx * 8), sb1 = swz(tx * 8 + 4);

    float4 av = *(const float4*)Ap;
    float4 wv = *(const float4*)Wp;
    if (BNA) {
        float4 sc = *(const float4*)&g_scale[lc];
        float4 sh = *(const float4*)&g_shift[lc];
        av.x = fmaxf(av.x * sc.x + sh.x, 0.f);
        av.y = fmaxf(av.y * sc.y + sh.y, 0.f);
        av.z = fmaxf(av.z * sc.z + sh.z, 0.f);
        av.w = fmaxf(av.w * sc.w + sh.w, 0.f);
    }
    As[0][(lc + 0) * 132 + wp] = av.x; As[0][(lc + 1) * 132 + wp] = av.y;
    As[0][(lc + 2) * 132 + wp] = av.z; As[0][(lc + 3) * 132 + wp] = av.w;
    Bs[0][(lc + 0) * 132 + wp] = wv.x; Bs[0][(lc + 1) * 132 + wp] = wv.y;
    Bs[0][(lc + 2) * 132 + wp] = wv.z; Bs[0][(lc + 3) * 132 + wp] = wv.w;
    __syncthreads();

    ull acc2[8][4];
#pragma unroll
    for (int i = 0; i < 8; i++)
#pragma unroll
        for (int j = 0; j < 4; j++) acc2[i][j] = 0ull;

    constexpr int NIT = CIN / 8;
#pragma unroll 2
    for (int it = 0; it < NIT; it++) {
        int cur = it & 1;
        float4 av2, wv2;
        if (it + 1 < NIT) {
            av2 = *(const float4*)(Ap + (it + 1) * 8);
            wv2 = *(const float4*)(Wp + (it + 1) * 8);
            if (BNA) {
                float4 sc = *(const float4*)&g_scale[(it + 1) * 8 + lc];
                float4 sh = *(const float4*)&g_shift[(it + 1) * 8 + lc];
                av2.x = fmaxf(av2.x * sc.x + sh.x, 0.f);
                av2.y = fmaxf(av2.y * sc.y + sh.y, 0.f);
                av2.z = fmaxf(av2.z * sc.z + sh.z, 0.f);
                av2.w = fmaxf(av2.w * sc.w + sh.w, 0.f);
            }
        }
#pragma unroll
        for (int k = 0; k < 8; k++) {
            float4 a0 = *(const float4*)&As[cur][k * 132 + sa0];
            float4 a1 = *(const float4*)&As[cur][k * 132 + sa1];
            ulonglong2 bp0 = *(const ulonglong2*)&Bs[cur][k * 132 + sb0];
            ulonglong2 bp1 = *(const ulonglong2*)&Bs[cur][k * 132 + sb1];
            float a[8] = {a0.x, a0.y, a0.z, a0.w, a1.x, a1.y, a1.z, a1.w};
            ull bp[4] = {bp0.x, bp0.y, bp1.x, bp1.y};
#pragma unroll
            for (int i = 0; i < 8; i++) {
                ull as = splat2(a[i]);
#pragma unroll
                for (int j = 0; j < 4; j++) ffma2(acc2[i][j], as, bp[j]);
            }
        }
        if (it + 1 < NIT) {
            int nxt = 1 - cur;
            As[nxt][(lc + 0) * 132 + wp] = av2.x; As[nxt][(lc + 1) * 132 + wp] = av2.y;
            As[nxt][(lc + 2) * 132 + wp] = av2.z; As[nxt][(lc + 3) * 132 + wp] = av2.w;
            Bs[nxt][(lc + 0) * 132 + wp] = wv2.x; Bs[nxt][(lc + 1) * 132 + wp] = wv2.y;
            Bs[nxt][(lc + 2) * 132 + wp] = wv2.z; Bs[nxt][(lc + 3) * 132 + wp] = wv2.w;
            __syncthreads();
        }
    }
#pragma unroll
    for (int i = 0; i < 8; i++) {
        int r = brow + ty * 8 + i;
        float4* cp = (float4*)(C + (size_t)r * O + bcol + tx * 8);
        float2 p0 = unpk(acc2[i][0]), p1 = unpk(acc2[i][1]);
        float2 p2 = unpk(acc2[i][2]), p3 = unpk(acc2[i][3]);
        cp[0] = make_float4(p0.x, p0.y, p1.x, p1.y);
        cp[1] = make_float4(p2.x, p2.y, p3.x, p3.y);
    }
}

// ---------------- FUSED layer-2 GEMM — TF32 mma.sync tensor-core core ----------------
// A row = relu(bn(G[knn[row]] + C[center]))  (gathered on load, tf32-converted)
// Epilogue: per-center (32-row) raw max/min + per-col sum/sumsq. No C write.
template <int CIN, int STAGE>
__global__ __launch_bounds__(256) void gemm2_tf32(const float* __restrict__ W) {
    const float* G = g_zbuf;
    const float* C = (STAGE == 0) ? g_c1out : g_c2out;
    const int* knn = (STAGE == 0) ? g_knn1 : g_knn2;
    constexpr int NPTS = (STAGE == 0) ? NN : S1V;
    constexpr int BSH = (STAGE == 0) ? 9 : 8;

    __shared__ __align__(16) uint As[2][128 * 12];   // [row][k] tf32, stride 12
    __shared__ __align__(16) uint Bs[2][128 * 12];   // [ocol][k] tf32
    __shared__ float red[4 * 8 * 132];               // [center][g][col]

    int tid = threadIdx.x;
    int brow = blockIdx.x * 128, bcol = blockIdx.y * 128;
    int lane = tid & 31, wid = tid >> 5;
    int wm = wid >> 2, wn = wid & 3;                 // warp tile: 64 rows x 32 cols
    int g = lane >> 2, q = lane & 3;

    int lr = tid >> 1, lc = (tid & 1) * 4;           // loader: row lr, k-cols lc..lc+3
    int grow = brow + lr;
    int nb = knn[grow];
    int bs = grow >> 5;
    int b = bs >> BSH;
    const float* Gp = G + ((size_t)(b * NPTS + nb)) * CIN + lc;
    const float* Cp = C + (size_t)bs * CIN + lc;
    const float* Wp = W + (size_t)(bcol + lr) * CIN + lc;

    auto loadA = [&](int k0) -> uint4 {
        float4 gv = *(const float4*)(Gp + k0);
        float4 cv = *(const float4*)(Cp + k0);
        float4 sc = *(const float4*)&g_scale[k0 + lc];
        float4 sh = *(const float4*)&g_shift[k0 + lc];
        uint4 r;
        r.x = totf32(fmaxf((gv.x + cv.x) * sc.x + sh.x, 0.f));
        r.y = totf32(fmaxf((gv.y + cv.y) * sc.y + sh.y, 0.f));
        r.z = totf32(fmaxf((gv.z + cv.z) * sc.z + sh.z, 0.f));
        r.w = totf32(fmaxf((gv.w + cv.w) * sc.w + sh.w, 0.f));
        return r;
    };
    auto loadB = [&](int k0) -> uint4 {
        float4 wv = *(const float4*)(Wp + k0);
        uint4 r;
        r.x = totf32(wv.x); r.y = totf32(wv.y); r.z = totf32(wv.z); r.w = totf32(wv.w);
        return r;
    };

    // panel 0
    {
        uint4 a = loadA(0);
        uint4 w = loadB(0);
        *(uint4*)&As[0][lr * 12 + lc] = a;
        *(uint4*)&Bs[0][lr * 12 + lc] = w;
    }
    __syncthreads();

    float acc[4][4][4];
#pragma unroll
    for (int mi = 0; mi < 4; mi++)
#pragma unroll
        for (int ni = 0; ni < 4; ni++)
#pragma unroll
            for (int r = 0; r < 4; r++) acc[mi][ni][r] = 0.f;

    constexpr int NIT = CIN / 8;
    for (int it = 0; it < NIT; it++) {
        int cur = it & 1;
        uint4 pa, pw;
        if (it + 1 < NIT) {
            pa = loadA((it + 1) * 8);
            pw = loadB((it + 1) * 8);
        }
        // fragments
        uint a[4][4], bfr[4][2];
#pragma unroll
        for (int mi = 0; mi < 4; mi++) {
            int r0 = wm * 64 + mi * 16;
            a[mi][0] = As[cur][(r0 + g) * 12 + q];
            a[mi][1] = As[cur][(r0 + 8 + g) * 12 + q];
            a[mi][2] = As[cur][(r0 + g) * 12 + q + 4];
            a[mi][3] = As[cur][(r0 + 8 + g) * 12 + q + 4];
        }
#pragma unroll
        for (int ni = 0; ni < 4; ni++) {
            int n0 = wn * 32 + ni * 8;
            bfr[ni][0] = Bs[cur][(n0 + g) * 12 + q];
            bfr[ni][1] = Bs[cur][(n0 + g) * 12 + q + 4];
        }
#pragma unroll
        for (int mi = 0; mi < 4; mi++)
#pragma unroll
            for (int ni = 0; ni < 4; ni++) {
                asm volatile(
                    "mma.sync.aligned.m16n8k8.row.col.f32.tf32.tf32.f32 "
                    "{%0,%1,%2,%3}, {%4,%5,%6,%7}, {%8,%9}, {%0,%1,%2,%3};"
                    : "+f"(acc[mi][ni][0]), "+f"(acc[mi][ni][1]),
                      "+f"(acc[mi][ni][2]), "+f"(acc[mi][ni][3])
                    : "r"(a[mi][0]), "r"(a[mi][1]), "r"(a[mi][2]), "r"(a[mi][3]),
                      "r"(bfr[ni][0]), "r"(bfr[ni][1]));
            }
        if (it + 1 < NIT) {
            int nxt = 1 - cur;
            *(uint4*)&As[nxt][lr * 12 + lc] = pa;
            *(uint4*)&Bs[nxt][lr * 12 + lc] = pw;
            __syncthreads();
        }
    }

    // ---- epilogue: 4 staged passes (max, min, sum, sumsq) ----
    // fragment (mi, ni) rows all lie in center 2*wm + (mi>>1); thread's 4 regs at
    // rows {g, g+8} of bands mi=2ci, 2ci+1 -> combine 4 regs per (ci, ni, halfcol).
    int bs0 = brow >> 5;
#pragma unroll
    for (int pass = 0; pass < 4; pass++) {
        __syncthreads();
#pragma unroll
        for (int ci = 0; ci < 2; ci++) {
            int center = 2 * wm + ci;
#pragma unroll
            for (int ni = 0; ni < 4; ni++) {
#pragma unroll
                for (int h = 0; h < 2; h++) {
                    int col = wn * 32 + ni * 8 + 2 * q + h;
                    float v0 = acc[2 * ci][ni][h],     v1 = acc[2 * ci][ni][h + 2];
                    float v2 = acc[2 * ci + 1][ni][h], v3 = acc[2 * ci + 1][ni][h + 2];
                    float val;
                    if (pass == 0)      val = fmaxf(fmaxf(v0, v1), fmaxf(v2, v3));
                    else if (pass == 1) val = fminf(fminf(v0, v1), fminf(v2, v3));
                    else if (pass == 2) val = v0 + v1 + v2 + v3;
                    else                val = v0 * v0 + v1 * v1 + v2 * v2 + v3 * v3;
                    red[(center * 8 + g) * 132 + col] = val;
                }
            }
        }
        __syncthreads();
        if (pass == 0 || pass == 1) {
#pragma unroll
            for (int u = 0; u < 2; u++) {
                int o = tid + u * 256;          // 512 outputs: center*128+col
                int center = o >> 7, col = o & 127;
                float m = red[(center * 8) * 132 + col];
#pragma unroll
                for (int v = 1; v < 8; v++) {
                    float w = red[(center * 8 + v) * 132 + col];
                    m = (pass == 0) ? fmaxf(m, w) : fminf(m, w);
                }
                size_t oo = (size_t)(bs0 + center) * CIN + bcol + col;
                if (pass == 0) g_pmax[oo] = m; else g_pmin[oo] = m;
            }
        } else if (tid < 128) {
            int col = tid;
            float s = 0.f;
#pragma unroll
            for (int v = 0; v < 32; v++) s += red[v * 132 + col];
            if (pass == 2) atomicAdd(&g_sum[bcol + col], s);
            else atomicAdd(&g_sumsq[bcol + col], s);
        }
    }
}

// ---------------- gather-stats for y = G[nb] + C[center] ----------------
template <int CIN, int STAGE>
__global__ void stats_gather_k(int R) {
    const float* G = g_zbuf;
    const float* C = (STAGE == 0) ? g_c1out : g_c2out;
    const int* knn = (STAGE == 0) ? g_knn1 : g_knn2;
    constexpr int NPTS = (STAGE == 0) ? NN : S1V;
    constexpr int BSH = (STAGE == 0) ? 9 : 8;
    constexpr int NSEG = CIN / 128;

    int wid = (blockIdx.x * blockDim.x + threadIdx.x) >> 5;
    int lane = threadIdx.x & 31;
    int nw = (gridDim.x * blockDim.x) >> 5;
    float s[NSEG][4], q[NSEG][4];
#pragma unroll
    for (int sg = 0; sg < NSEG; sg++)
#pragma unroll
        for (int j = 0; j < 4; j++) { s[sg][j] = 0.f; q[sg][j] = 0.f; }

    for (int row = wid; row < R; row += nw) {
        int nb = knn[row];
        int bs = row >> 5;
        int b = bs >> BSH;
        size_t gb = ((size_t)(b * NPTS + nb)) * CIN;
        size_t cb = (size_t)bs * CIN;
#pragma unroll
        for (int sg = 0; sg < NSEG; sg++) {
            int col = sg * 128 + lane * 4;
            float4 g = *(const float4*)(G + gb + col);
            float4 c = *(const float4*)(C + cb + col);
            float y0 = g.x + c.x, y1 = g.y + c.y, y2 = g.z + c.z, y3 = g.w + c.w;
            s[sg][0] += y0; s[sg][1] += y1; s[sg][2] += y2; s[sg][3] += y3;
            q[sg][0] += y0 * y0; q[sg][1] += y1 * y1; q[sg][2] += y2 * y2; q[sg][3] += y3 * y3;
        }
    }
    __shared__ float ss[CIN], sq[CIN];
    for (int t = threadIdx.x; t < CIN; t += 256) { ss[t] = 0.f; sq[t] = 0.f; }
    __syncthreads();
#pragma unroll
    for (int sg = 0; sg < NSEG; sg++)
#pragma unroll
        for (int j = 0; j < 4; j++) {
            atomicAdd(&ss[sg * 128 + lane * 4 + j], s[sg][j]);
            atomicAdd(&sq[sg * 128 + lane * 4 + j], q[sg][j]);
        }
    __syncthreads();
    for (int t = threadIdx.x; t < CIN; t += 256) {
        atomicAdd(&g_sum[t], ss[t]);
        atomicAdd(&g_sumsq[t], sq[t]);
    }
}

// ---------------- weight diffs ----------------
__global__ void wdiff1_k(const float* __restrict__ w) {
    int i = blockIdx.x * 256 + threadIdx.x;
    int o = i >> 6, d = i & 63;
    g_wdiff1[i] = w[o * 128 + 64 + d] - w[o * 128 + d];
}
__global__ void wdiff2_k(const float* __restrict__ w) {
    int i = blockIdx.x * 256 + threadIdx.x;
    int o = i >> 7, d = i & 127;
    g_wdiff2[i] = w[o * 256 + 128 + d] - w[o * 256 + d];
}

// ---------------- center feature gathers ----------------
__global__ void gather_cfeat1() {
    int i = blockIdx.x * 256 + threadIdx.x;
    int r = i >> 6, c = i & 63;
    int b = r >> 9;
    int fid = g_fidx1[r];
    float v = g_f[((size_t)(b * NN + fid)) * 64 + c];
    g_cfeat1[i] = fmaxf(v * g_scale[c] + g_shift[c], 0.f);
}
__global__ void gather_cfeat2() {
    int i = blockIdx.x * 256 + threadIdx.x;
    int r = i >> 7, c = i & 127;
    int b = r >> 8;
    int fid = g_fidx2[r];
    g_cfeat2[i] = g_f1[((size_t)(b * S1V + fid)) * 128 + c];
}

// ---------------- pool finish ----------------
__global__ void pool_finish1() {
    int i = blockIdx.x * 256 + threadIdx.x;
    int c = i & 127;
    float sc = g_scale[c];
    float v = (sc >= 0.f) ? g_pmax[i] : g_pmin[i];
    g_f1[i] = fmaxf(sc * v + g_shift[c], 0.f);
}
__global__ void pool_finish2(float* __restrict__ out) {
    int i = blockIdx.x * 256 + threadIdx.x;
    int bs = i >> 8, o = i & 255;
    int b = bs >> 8, s = bs & 255;
    float sc = g_scale[o];
    float v = (sc >= 0.f) ? g_pmax[i] : g_pmin[i];
    out[((size_t)(b * 256 + o)) * 256 + s] = fmaxf(sc * v + g_shift[o], 0.f);
}

// ---------------- launch sequence (triple-stream DAG) ----------------
extern "C" void kernel_launch(void* const* d_in, const int* in_sizes, int n_in,
                              void* d_out, int out_size) {
    const float* x     = (const float*)d_in[0];
    const float* w1    = (const float*)d_in[1];
    const float* w2    = (const float*)d_in[2];
    const float* g1    = (const float*)d_in[3];
    const float* b1    = (const float*)d_in[4];
    const float* g2    = (const float*)d_in[5];
    const float* b2    = (const float*)d_in[6];
    const float* s1w1  = (const float*)d_in[7];
    const float* s1w2  = (const float*)d_in[8];
    const float* s1g1  = (const float*)d_in[9];
    const float* s1b1  = (const float*)d_in[10];
    const float* s1g2  = (const float*)d_in[11];
    const float* s1b2  = (const float*)d_in[12];
    const float* s2w1  = (const float*)d_in[13];
    const float* s2w2  = (const float*)d_in[14];
    const float* s2g1  = (const float*)d_in[15];
    const float* s2b1  = (const float*)d_in[16];
    const float* s2g2  = (const float*)d_in[17];
    const float* s2b2  = (const float*)d_in[18];
    float* out = (float*)d_out;

    const int RP = BB * NN;
    const int R1 = BB * S1V * KV;
    const int R2 = BB * S2V * KV;

    static cudaStream_t sA = nullptr, sB = nullptr;
    static cudaEvent_t ev_prep = nullptr, ev_fps1 = nullptr, ev_gc2 = nullptr,
                       ev_knn1 = nullptr, ev_fps2 = nullptr, ev_knn2 = nullptr;
    if (!sA) {
        cudaStreamCreateWithFlags(&sA, cudaStreamNonBlocking);
        cudaStreamCreateWithFlags(&sB, cudaStreamNonBlocking);
        cudaEventCreateWithFlags(&ev_prep, cudaEventDisableTiming);
        cudaEventCreateWithFlags(&ev_fps1, cudaEventDisableTiming);
        cudaEventCreateWithFlags(&ev_gc2, cudaEventDisableTiming);
        cudaEventCreateWithFlags(&ev_knn1, cudaEventDisableTiming);
        cudaEventCreateWithFlags(&ev_fps2, cudaEventDisableTiming);
        cudaEventCreateWithFlags(&ev_knn2, cudaEventDisableTiming);
    }
    cudaStream_t m = 0;

    // --- main: coords ---
    prep_coords<<<RP / 256, 256, 0, m>>>(x);
    cudaEventRecord(ev_prep, m);

    // --- stream A: fps1 -> gather_c2 -> knn1 ---
    cudaStreamWaitEvent(sA, ev_prep, 0);
    fps_kernel<NN, S1V, 1024, 0><<<BB, 1024, 0, sA>>>();
    cudaEventRecord(ev_fps1, sA);
    gather_c2<<<BB * S1V / 256, 256, 0, sA>>>();
    cudaEventRecord(ev_gc2, sA);
    knn_kernel<NN, S1V, 0><<<BB * S1V / 4, 128, 0, sA>>>();
    cudaEventRecord(ev_knn1, sA);

    // --- stream B: fps2 -> knn2 (concurrent with knn1) ---
    cudaStreamWaitEvent(sB, ev_gc2, 0);
    fps_kernel<S1V, S2V, 512, 1><<<BB, 512, 0, sB>>>();
    cudaEventRecord(ev_fps2, sB);
    knn_kernel<S1V, S2V, 1><<<BB * S2V / 4, 128, 0, sB>>>();
    cudaEventRecord(ev_knn2, sB);

    // --- main: feature chain ---
    cbr1_kernel<<<512, 256, 0, m>>>(x, w1);
    finalize_stats<<<1, 256, 0, m>>>(g1, b1, 1.0f / RP, 64);
    cbr2_kernel<<<512, 256, 0, m>>>(w2);
    finalize_stats<<<1, 256, 0, m>>>(g2, b2, 1.0f / RP, 64);

    gemm_k<64, 128, true><<<dim3(512, 1), 256, 0, m>>>(2, s1w1, -1, 0, 128);
    wdiff1_k<<<128 * 64 / 256, 256, 0, m>>>(s1w1);
    cudaStreamWaitEvent(m, ev_fps1, 0);
    gather_cfeat1<<<BB * S1V * 64 / 256, 256, 0, m>>>();
    gemm_k<64, 64, false><<<dim3(64, 1), 256, 0, m>>>(3, nullptr, 7, 5, 128);

    cudaStreamWaitEvent(m, ev_knn1, 0);
    stats_gather_k<128, 0><<<512, 256, 0, m>>>(R1);
    finalize_stats<<<1, 256, 0, m>>>(s1g1, s1b1, 1.0f / R1, 128);

    gemm2_tf32<128, 0><<<dim3(2048, 1), 256, 0, m>>>(s1w2);
    finalize_stats<<<1, 256, 0, m>>>(s1g2, s1b2, 1.0f / R1, 128);
    pool_finish1<<<BB * S1V * 128 / 256, 256, 0, m>>>();

    gemm_k<128, 256, false><<<dim3(64, 2), 256, 0, m>>>(9, s2w1, -1, 0, 256);
    wdiff2_k<<<256 * 128 / 256, 256, 0, m>>>(s2w1);
    cudaStreamWaitEvent(m, ev_fps2, 0);
    gather_cfeat2<<<BB * S2V * 128 / 256, 256, 0, m>>>();
    gemm_k<128, 128, false><<<dim3(32, 2), 256, 0, m>>>(4, nullptr, 8, 6, 256);

    cudaStreamWaitEvent(m, ev_knn2, 0);
    stats_gather_k<256, 1><<<512, 256, 0, m>>>(R2);
    finalize_stats<<<1, 256, 0, m>>>(s2g1, s2b1, 1.0f / R2, 256);

    gemm2_tf32<256, 1><<<dim3(1024, 2), 256, 0, m>>>(s2w2);
    finalize_stats<<<1, 256, 0, m>>>(s2g2, s2b2, 1.0f / R2, 256);
    pool_finish2<<<BB * S2V * 256 / 256, 256, 0, m>>>(out);
}